// round 14
// baseline (speedup 1.0000x reference)
#include <cuda_runtime.h>
#include <cstdint>

#define NN 100000
#define NE 800000
typedef unsigned long long u64;

// ---------------- device scratch ----------------
__device__ __align__(16) float  g_hcur[NN * 8];
__device__ __align__(16) float g_qp[(size_t)NN * 128];  // Q1|Q2 (then P1|P2)
__device__ __align__(16) float g_u3[(size_t)NN * 64];   // cx@Wu1_top + bu1
__device__ __align__(16) float g_hsum[(size_t)NN * 64]; // Hsum1 then Hsum2
// CSR structures (built once per call; bucket order across nodes arbitrary)
__device__ int g_deg_src[NN], g_deg_tgt[NN];
__device__ int g_offs_src[NN], g_offs_tgt[NN];
__device__ int g_cur_src[NN], g_cur_tgt[NN];
__device__ int g_ctr[2];
__device__ float4 g_csr_src[NE];   // (tgt as int bits, ef0, ef1, ef2)
__device__ int    g_csr_tgt[NE];   // src
// folded weights
__device__ float g_wbig[64 * 192]; // We2 @ [Wm1_top | Wm1_bot | Wu1_top]
__device__ float g_bvec[192];      // be2 @ same
__device__ float g_cvec[192];      // [bm1 | 0 | bu1]
__device__ float g_w2u[4096];      // Wm2 @ Wu1[64:128]
__device__ float g_vb[64];         // bm2 @ Wu1[64:128]
__device__ float g_wud[4096];      // Wu2 @ Wd1
__device__ float g_bud[64];        // bu2 @ Wd1 + bd1

// ---------------- f32x2 helpers ----------------
__device__ __forceinline__ u64 pk2(float x) {
    u64 d; asm("mov.b64 %0, {%1, %1};" : "=l"(d) : "f"(x)); return d;
}
__device__ __forceinline__ u64 f2(u64 a, u64 b, u64 c) {
    u64 d; asm("fma.rn.f32x2 %0, %1, %2, %3;" : "=l"(d) : "l"(a), "l"(b), "l"(c)); return d;
}
__device__ __forceinline__ float2 up2(u64 a) {
    float2 r; asm("mov.b64 {%0, %1}, %2;" : "=f"(r.x), "=f"(r.y) : "l"(a)); return r;
}

// C[64 x cols] += A^T B ; A k-major As[k*AP+row], B Bs[k*BP+col]; 4x4 microtile
template<int K, int AP, int BP>
__device__ __forceinline__ void mmacc(const float* As, const float* Bs,
                                      u64 acc[4][2], int e4, int c4) {
#pragma unroll 8
    for (int k = 0; k < K; k++) {
        float4 a = *(const float4*)(As + k * AP + e4);
        ulonglong2 b = *(const ulonglong2*)(Bs + k * BP + c4);
        u64 a0 = pk2(a.x), a1 = pk2(a.y), a2 = pk2(a.z), a3 = pk2(a.w);
        acc[0][0] = f2(a0, b.x, acc[0][0]); acc[0][1] = f2(a0, b.y, acc[0][1]);
        acc[1][0] = f2(a1, b.x, acc[1][0]); acc[1][1] = f2(a1, b.y, acc[1][1]);
        acc[2][0] = f2(a2, b.x, acc[2][0]); acc[2][1] = f2(a2, b.y, acc[2][1]);
        acc[3][0] = f2(a3, b.x, acc[3][0]); acc[3][1] = f2(a3, b.y, acc[3][1]);
    }
}

// ---------------- setup kernels ----------------
__global__ void k_init(const float* __restrict__ h0) {
    int i = blockIdx.x * blockDim.x + threadIdx.x;
    if (i < NN * 8) g_hcur[i] = h0[i];
    if (i < NN) { g_deg_src[i] = 0; g_deg_tgt[i] = 0; }
    if (i == 0) { g_ctr[0] = 0; g_ctr[1] = 0; }
}
__global__ void k_deg(const int* __restrict__ src, const int* __restrict__ tgt) {
    int e = blockIdx.x * blockDim.x + threadIdx.x;
    if (e < NE) {
        atomicAdd(&g_deg_src[src[e]], 1);
        atomicAdd(&g_deg_tgt[tgt[e]], 1);
    }
}
__global__ void k_alloc() {
    int n = blockIdx.x * blockDim.x + threadIdx.x;
    if (n < NN) {
        int o0 = atomicAdd(&g_ctr[0], g_deg_src[n]);
        g_offs_src[n] = o0; g_cur_src[n] = o0;
        int o1 = atomicAdd(&g_ctr[1], g_deg_tgt[n]);
        g_offs_tgt[n] = o1; g_cur_tgt[n] = o1;
    }
}
__global__ void k_fill(const int* __restrict__ src, const int* __restrict__ tgt,
                       const float* __restrict__ ef) {
    int e = blockIdx.x * blockDim.x + threadIdx.x;
    if (e >= NE) return;
    int s = src[e], t = tgt[e];
    float f0 = ef[(size_t)e * 3], f1 = ef[(size_t)e * 3 + 1], f2v = ef[(size_t)e * 3 + 2];
    int p = atomicAdd(&g_cur_src[s], 1);
    g_csr_src[p] = make_float4(__int_as_float(t), f0, f1, f2v);
    int q = atomicAdd(&g_cur_tgt[t], 1);
    g_csr_tgt[q] = s;
}
// weight folding
__global__ void k_wprep(const float* __restrict__ We2, const float* __restrict__ be2,
                        const float* __restrict__ Wm1, const float* __restrict__ bm1,
                        const float* __restrict__ Wm2, const float* __restrict__ bm2,
                        const float* __restrict__ Wu1, const float* __restrict__ bu1,
                        const float* __restrict__ Wu2, const float* __restrict__ bu2,
                        const float* __restrict__ Wd1, const float* __restrict__ bd1) {
    int idx = blockIdx.x * blockDim.x + threadIdx.x;
    if (idx < 12288) {
        int g = idx >> 12, rem = idx & 4095;
        int r = rem >> 6, c = rem & 63;
        const float* W = (g == 0) ? Wm1 : (g == 1) ? (Wm1 + 64 * 64) : Wu1;
        float s = 0.f;
#pragma unroll 8
        for (int b = 0; b < 64; b++) s += We2[r * 64 + b] * W[b * 64 + c];
        g_wbig[r * 192 + g * 64 + c] = s;
    } else if (idx < 12480) {
        int j = idx - 12288;
        int g = j >> 6, c = j & 63;
        const float* W = (g == 0) ? Wm1 : (g == 1) ? (Wm1 + 64 * 64) : Wu1;
        float s = 0.f;
#pragma unroll 8
        for (int b = 0; b < 64; b++) s += be2[b] * W[b * 64 + c];
        g_bvec[j] = s;
        g_cvec[j] = (g == 0) ? bm1[c] : (g == 2) ? bu1[c] : 0.f;
    } else if (idx < 16576) {
        int k = idx - 12480;
        int a = k >> 6, c = k & 63;
        float s = 0.f;
#pragma unroll 8
        for (int b = 0; b < 64; b++) s += Wm2[a * 64 + b] * Wu1[(64 + b) * 64 + c];
        g_w2u[k] = s;
    } else if (idx < 16640) {
        int c = idx - 16576;
        float s = 0.f;
#pragma unroll 8
        for (int b = 0; b < 64; b++) s += bm2[b] * Wu1[(64 + b) * 64 + c];
        g_vb[c] = s;
    } else if (idx < 20736) {
        int k = idx - 16640;
        int a = k >> 6, c = k & 63;
        float s = 0.f;
#pragma unroll 8
        for (int b = 0; b < 64; b++) s += Wu2[a * 64 + b] * Wd1[b * 64 + c];
        g_wud[k] = s;
    } else if (idx < 20800) {
        int c = idx - 20736;
        float s = bd1[c];
#pragma unroll 8
        for (int b = 0; b < 64; b++) s += bu2[b] * Wd1[b * 64 + c];
        g_bud[c] = s;
    }
}

// ------------- Q1 = nf@We1[3:24]+be1, Q2 = nf@We1[24:45]; nf built inline -------------
__global__ void __launch_bounds__(256) k_qp1(const float* __restrict__ We1,
                                             const float* __restrict__ be1,
                                             const float* __restrict__ runoff,
                                             const float* __restrict__ elev,
                                             int step) {
    __shared__ float Wq[24 * 128];
    __shared__ float A[24 * 64];
    __shared__ float b1s[64];
    const int tid = threadIdx.x;
    const int tx = tid & 15, ty = tid >> 4;
    const int c4 = tx * 4, e4 = ty * 4;

    for (int i = tid; i < 24 * 128; i += 256) {
        int r = i >> 7, c = i & 127;
        float v = 0.f;
        if (r < 21) v = (c < 64) ? We1[(3 + r) * 64 + c] : We1[(24 + r) * 64 + (c - 64)];
        Wq[i] = v;
    }
    if (tid < 64) b1s[tid] = be1[tid];

    const int ntiles = (NN + 63) / 64;
    for (int tile = blockIdx.x; tile < ntiles; tile += gridDim.x) {
        int n0 = tile * 64;
        __syncthreads();
        for (int i = tid; i < 384; i += 256) {
            int e = i & 63, q = i >> 6;
            int n = min(n0 + e, NN - 1);
            float4 v;
            if (q < 2)      v = *(const float4*)(g_hcur + n * 8 + q * 4);
            else if (q < 5) v = *(const float4*)(runoff + (size_t)n * 24 + step + (q - 2) * 4);
            else            v = make_float4(elev[n], 0.f, 0.f, 0.f);
            A[(q * 4 + 0) * 64 + e] = v.x; A[(q * 4 + 1) * 64 + e] = v.y;
            A[(q * 4 + 2) * 64 + e] = v.z; A[(q * 4 + 3) * 64 + e] = v.w;
        }
        __syncthreads();
        u64 acc0[4][2] = {}, acc1[4][2] = {};
        mmacc<24, 64, 128>(A, Wq, acc0, e4, c4);
        mmacc<24, 64, 128>(A, Wq + 64, acc1, e4, c4);
        float4 bb = *(const float4*)&b1s[c4];
#pragma unroll
        for (int i = 0; i < 4; i++) {
            int n = n0 + e4 + i;
            if (n < NN) {
                float2 p0 = up2(acc0[i][0]), p1 = up2(acc0[i][1]);
                *(float4*)(g_qp + (size_t)n * 128 + c4) =
                    make_float4(p0.x + bb.x, p0.y + bb.y, p1.x + bb.z, p1.y + bb.w);
                float2 r0 = up2(acc1[i][0]), r1 = up2(acc1[i][1]);
                *(float4*)(g_qp + (size_t)n * 128 + 64 + c4) =
                    make_float4(r0.x, r0.y, r1.x, r1.y);
            }
        }
    }
}

// ------------- edge pass 1 (4-way unrolled): Hsum1[n] = sum relu(Q1[n]+Q2[t]+ef@Wef) ------
__global__ void __launch_bounds__(256) k_edge1(const float* __restrict__ We1) {
    const int l = threadIdx.x & 15;
    const int gstride = gridDim.x * (blockDim.x >> 4);
    int n = blockIdx.x * (blockDim.x >> 4) + (threadIdx.x >> 4);
    const int c4 = l * 4;
    const float4 w0 = *(const float4*)(We1 + c4);
    const float4 w1 = *(const float4*)(We1 + 64 + c4);
    const float4 w2 = *(const float4*)(We1 + 128 + c4);
    const float4* __restrict__ gq = (const float4*)g_qp;

    for (; n < NN; n += gstride) {
        float4 q1 = gq[(size_t)n * 32 + l];
        int off = g_offs_src[n], end = off + g_deg_src[n];
        float4 acc = make_float4(0.f, 0.f, 0.f, 0.f);
        int i = off;
        for (; i + 4 <= end; i += 4) {
            float4 t0 = g_csr_src[i];
            float4 t1 = g_csr_src[i + 1];
            float4 t2 = g_csr_src[i + 2];
            float4 t3 = g_csr_src[i + 3];
            float4 a0 = gq[(size_t)__float_as_int(t0.x) * 32 + 16 + l];
            float4 a1 = gq[(size_t)__float_as_int(t1.x) * 32 + 16 + l];
            float4 a2 = gq[(size_t)__float_as_int(t2.x) * 32 + 16 + l];
            float4 a3 = gq[(size_t)__float_as_int(t3.x) * 32 + 16 + l];
            acc.x += fmaxf(q1.x + a0.x + t0.y * w0.x + t0.z * w1.x + t0.w * w2.x, 0.f);
            acc.y += fmaxf(q1.y + a0.y + t0.y * w0.y + t0.z * w1.y + t0.w * w2.y, 0.f);
            acc.z += fmaxf(q1.z + a0.z + t0.y * w0.z + t0.z * w1.z + t0.w * w2.z, 0.f);
            acc.w += fmaxf(q1.w + a0.w + t0.y * w0.w + t0.z * w1.w + t0.w * w2.w, 0.f);
            acc.x += fmaxf(q1.x + a1.x + t1.y * w0.x + t1.z * w1.x + t1.w * w2.x, 0.f);
            acc.y += fmaxf(q1.y + a1.y + t1.y * w0.y + t1.z * w1.y + t1.w * w2.y, 0.f);
            acc.z += fmaxf(q1.z + a1.z + t1.y * w0.z + t1.z * w1.z + t1.w * w2.z, 0.f);
            acc.w += fmaxf(q1.w + a1.w + t1.y * w0.w + t1.z * w1.w + t1.w * w2.w, 0.f);
            acc.x += fmaxf(q1.x + a2.x + t2.y * w0.x + t2.z * w1.x + t2.w * w2.x, 0.f);
            acc.y += fmaxf(q1.y + a2.y + t2.y * w0.y + t2.z * w1.y + t2.w * w2.y, 0.f);
            acc.z += fmaxf(q1.z + a2.z + t2.y * w0.z + t2.z * w1.z + t2.w * w2.z, 0.f);
            acc.w += fmaxf(q1.w + a2.w + t2.y * w0.w + t2.z * w1.w + t2.w * w2.w, 0.f);
            acc.x += fmaxf(q1.x + a3.x + t3.y * w0.x + t3.z * w1.x + t3.w * w2.x, 0.f);
            acc.y += fmaxf(q1.y + a3.y + t3.y * w0.y + t3.z * w1.y + t3.w * w2.y, 0.f);
            acc.z += fmaxf(q1.z + a3.z + t3.y * w0.z + t3.z * w1.z + t3.w * w2.z, 0.f);
            acc.w += fmaxf(q1.w + a3.w + t3.y * w0.w + t3.z * w1.w + t3.w * w2.w, 0.f);
        }
        for (; i < end; i++) {
            float4 te = g_csr_src[i];
            float4 q2 = gq[(size_t)__float_as_int(te.x) * 32 + 16 + l];
            acc.x += fmaxf(q1.x + q2.x + te.y * w0.x + te.z * w1.x + te.w * w2.x, 0.f);
            acc.y += fmaxf(q1.y + q2.y + te.y * w0.y + te.z * w1.y + te.w * w2.y, 0.f);
            acc.z += fmaxf(q1.z + q2.z + te.y * w0.z + te.z * w1.z + te.w * w2.z, 0.f);
            acc.w += fmaxf(q1.w + q2.w + te.y * w0.w + te.z * w1.w + te.w * w2.w, 0.f);
        }
        *(float4*)(g_hsum + (size_t)n * 64 + c4) = acc;
    }
}

// ------------- fused, persistent per-group blocks: one 64-col group per block -------------
// smem floats: Wg 4096 | A 64x68=4352 | bvs 64 | cvs 64  => 8576 (34.3 KB, ~6 CTAs/SM)
#define SMEM_FUSE (8576 * 4)
#define FUSE_GRID 888   // 3 groups x 296 blocks
__global__ void __launch_bounds__(256) k_fuse() {
    extern __shared__ __align__(16) float sm[];
    float* Wg  = sm;            // 64x64 slice of wbig (k-major, stride 64)
    float* A   = sm + 4096;     // 64x68
    float* bvs = sm + 8448;
    float* cvs = sm + 8512;

    const int tid = threadIdx.x;
    const int tx = tid & 15, ty = tid >> 4;
    const int c4 = tx * 4, e4 = ty * 4;
    const int g = blockIdx.x % 3;
    const int bstart = blockIdx.x / 3;
    const int bstride = gridDim.x / 3;

    // stage this group's weight slice and biases ONCE
    for (int i = tid; i < 4096; i += 256) {
        int k = i >> 6, c = i & 63;
        Wg[i] = g_wbig[k * 192 + g * 64 + c];
    }
    if (tid < 64) { bvs[tid] = g_bvec[g * 64 + tid]; cvs[tid] = g_cvec[g * 64 + tid]; }

    const int ntiles = (NN + 63) / 64;
    for (int tile = bstart; tile < ntiles; tile += bstride) {
        int n0 = tile * 64;
        __syncthreads();
        for (int i = tid; i < 1024; i += 256) {
            int e = i & 63, q = i >> 6;
            int n = min(n0 + e, NN - 1);
            float4 v = *(const float4*)(g_hsum + (size_t)n * 64 + q * 4);
            A[(q * 4 + 0) * 68 + e] = v.x; A[(q * 4 + 1) * 68 + e] = v.y;
            A[(q * 4 + 2) * 68 + e] = v.z; A[(q * 4 + 3) * 68 + e] = v.w;
        }
        __syncthreads();
        u64 acc[4][2] = {};
        mmacc<64, 68, 64>(A, Wg, acc, e4, c4);
        float4 bv = *(const float4*)&bvs[c4];
        float4 cv = *(const float4*)&cvs[c4];
#pragma unroll
        for (int i = 0; i < 4; i++) {
            int n = n0 + e4 + i;
            if (n < NN) {
                float degf = (float)g_deg_src[n];
                float2 p0 = up2(acc[i][0]), p1 = up2(acc[i][1]);
                float4 o = make_float4(p0.x + degf * bv.x + cv.x,
                                       p0.y + degf * bv.y + cv.y,
                                       p1.x + degf * bv.z + cv.z,
                                       p1.y + degf * bv.w + cv.w);
                if (g == 0)      *(float4*)(g_qp + (size_t)n * 128 + c4) = o;
                else if (g == 1) *(float4*)(g_qp + (size_t)n * 128 + 64 + c4) = o;
                else             *(float4*)(g_u3 + (size_t)n * 64 + c4) = o;
            }
        }
    }
}

// ------------- edge pass 2 (4-way unrolled): Hsum2[n] = sum relu(P1[s]+P2[n]) -------------
__global__ void __launch_bounds__(256) k_edge2() {
    const int l = threadIdx.x & 15;
    const int gstride = gridDim.x * (blockDim.x >> 4);
    int n = blockIdx.x * (blockDim.x >> 4) + (threadIdx.x >> 4);
    const float4* __restrict__ gq = (const float4*)g_qp;

    for (; n < NN; n += gstride) {
        float4 p2 = gq[(size_t)n * 32 + 16 + l];
        int off = g_offs_tgt[n], end = off + g_deg_tgt[n];
        float4 acc = make_float4(0.f, 0.f, 0.f, 0.f);
        int i = off;
        for (; i + 4 <= end; i += 4) {
            int s0 = g_csr_tgt[i];
            int s1 = g_csr_tgt[i + 1];
            int s2 = g_csr_tgt[i + 2];
            int s3 = g_csr_tgt[i + 3];
            float4 a0 = gq[(size_t)s0 * 32 + l];
            float4 a1 = gq[(size_t)s1 * 32 + l];
            float4 a2 = gq[(size_t)s2 * 32 + l];
            float4 a3 = gq[(size_t)s3 * 32 + l];
            acc.x += fmaxf(a0.x + p2.x, 0.f) + fmaxf(a1.x + p2.x, 0.f)
                   + fmaxf(a2.x + p2.x, 0.f) + fmaxf(a3.x + p2.x, 0.f);
            acc.y += fmaxf(a0.y + p2.y, 0.f) + fmaxf(a1.y + p2.y, 0.f)
                   + fmaxf(a2.y + p2.y, 0.f) + fmaxf(a3.y + p2.y, 0.f);
            acc.z += fmaxf(a0.z + p2.z, 0.f) + fmaxf(a1.z + p2.z, 0.f)
                   + fmaxf(a2.z + p2.z, 0.f) + fmaxf(a3.z + p2.z, 0.f);
            acc.w += fmaxf(a0.w + p2.w, 0.f) + fmaxf(a1.w + p2.w, 0.f)
                   + fmaxf(a2.w + p2.w, 0.f) + fmaxf(a3.w + p2.w, 0.f);
        }
        for (; i < end; i++) {
            int s = g_csr_tgt[i];
            float4 p1 = gq[(size_t)s * 32 + l];
            acc.x += fmaxf(p1.x + p2.x, 0.f);
            acc.y += fmaxf(p1.y + p2.y, 0.f);
            acc.z += fmaxf(p1.z + p2.z, 0.f);
            acc.w += fmaxf(p1.w + p2.w, 0.f);
        }
        *(float4*)(g_hsum + (size_t)n * 64 + l * 4) = acc;
    }
}

// ---------------- node: 2 GEMMs (w2u, wud) + decoder + head (R9-proven) ----------------
#define SMEM_ND (17296 * 4)
__global__ void __launch_bounds__(256) k_node(
    const float* __restrict__ elev, const float* __restrict__ gl,
    const float* __restrict__ Wd2, const float* __restrict__ bd2,
    float* __restrict__ out, int sidx)
{
    extern __shared__ __align__(16) float sm[];
    float* W1   = sm;          float* W2  = sm + 4096;
    float* W4   = sm + 8192;
    float* vbs  = sm + 8448;   float* budv = sm + 8512;
    float* b4v  = sm + 8576;
    float* A    = sm + 8592;   float* Ps = A;
    float* Hs   = sm + 12944;

    const int tid = threadIdx.x;
    const int tx = tid & 15, ty = tid >> 4;
    const int c4 = tx * 4, e4 = ty * 4;

    for (int i = tid; i < 4096; i += 256) { W1[i] = g_w2u[i]; W2[i] = g_wud[i]; }
    if (tid < 256) W4[tid] = Wd2[tid];
    if (tid < 64) { vbs[tid] = g_vb[tid]; budv[tid] = g_bud[tid]; }
    if (tid < 4) b4v[tid] = bd2[tid];

    const int ntiles = (NN + 63) / 64;
    for (int tile = blockIdx.x; tile < ntiles; tile += gridDim.x) {
        int n0 = tile * 64;
        __syncthreads();
        for (int i = tid; i < 1024; i += 256) {
            int e = i & 63, q = i >> 6;
            int n = min(n0 + e, NN - 1);
            float4 v = *(const float4*)(g_hsum + (size_t)n * 64 + q * 4);
            A[(q * 4 + 0) * 68 + e] = v.x; A[(q * 4 + 1) * 68 + e] = v.y;
            A[(q * 4 + 2) * 68 + e] = v.z; A[(q * 4 + 3) * 68 + e] = v.w;
        }
        __syncthreads();
        u64 acc[4][2] = {};
        mmacc<64, 68, 64>(A, W1, acc, e4, c4);
        {
            float4 vv = *(const float4*)&vbs[c4];
            float hv[4][4];
#pragma unroll
            for (int i = 0; i < 4; i++) {
                int nc = min(n0 + e4 + i, NN - 1);
                float degf = (float)g_deg_tgt[nc];
                float4 u3 = *(const float4*)(g_u3 + (size_t)nc * 64 + c4);
                float2 p0 = up2(acc[i][0]), p1 = up2(acc[i][1]);
                hv[i][0] = fmaxf(p0.x + u3.x + degf * vv.x, 0.f);
                hv[i][1] = fmaxf(p0.y + u3.y + degf * vv.y, 0.f);
                hv[i][2] = fmaxf(p1.x + u3.z + degf * vv.z, 0.f);
                hv[i][3] = fmaxf(p1.y + u3.w + degf * vv.w, 0.f);
            }
            __syncthreads();
#pragma unroll
            for (int j = 0; j < 4; j++)
                *(float4*)&Hs[(c4 + j) * 68 + e4] = make_float4(hv[0][j], hv[1][j], hv[2][j], hv[3][j]);
        }
        __syncthreads();
        u64 acc2[4][2] = {};
        mmacc<64, 68, 64>(Hs, W2, acc2, e4, c4);
        {
            float4 bb = *(const float4*)&budv[c4];
            float pv[4][4];
#pragma unroll
            for (int i = 0; i < 4; i++) {
                float2 p0 = up2(acc2[i][0]), p1 = up2(acc2[i][1]);
                pv[i][0] = fmaxf(p0.x + bb.x, 0.f); pv[i][1] = fmaxf(p0.y + bb.y, 0.f);
                pv[i][2] = fmaxf(p1.x + bb.z, 0.f); pv[i][3] = fmaxf(p1.y + bb.w, 0.f);
            }
            __syncthreads();
#pragma unroll
            for (int j = 0; j < 4; j++)
                *(float4*)&Ps[(c4 + j) * 68 + e4] = make_float4(pv[0][j], pv[1][j], pv[2][j], pv[3][j]);
        }
        __syncthreads();
        // decoder 64->4 + head
        int node = tid >> 2, c = tid & 3;
        float dec = b4v[c];
#pragma unroll 8
        for (int k = 0; k < 64; k++) dec += Ps[k * 68 + node] * W4[k * 4 + c];

        int n = n0 + node;
        int nc = min(n, NN - 1);
        float ev  = elev[nc];
        float g   = gl[nc];
        float h7  = g_hcur[nc * 8 + 7];
        float old = g_hcur[nc * 8 + 4 + c];
        __syncwarp();
        if (n < NN) {
            float ph = 0.5f * dec + 0.5f * (h7 - ev) + ev;
            float pc = fminf(ph, g);
            float pl = fmaxf(pc, ev);
            out[(size_t)n * 16 + sidx * 4 + c] = pl;
            g_hcur[n * 8 + c]     = old;
            g_hcur[n * 8 + 4 + c] = pc;
        }
    }
}

// ---------------- launch ----------------
extern "C" void kernel_launch(void* const* d_in, const int* in_sizes, int n_in,
                              void* d_out, int out_size) {
    const float* h0     = (const float*)d_in[0];
    const float* runoff = (const float*)d_in[1];
    const float* elev   = (const float*)d_in[2];
    const float* gl     = (const float*)d_in[3];
    const float* ef     = (const float*)d_in[4];
    const int*   eix    = (const int*)d_in[5];
    const float* We1 = (const float*)d_in[7],  *be1 = (const float*)d_in[8];
    const float* We2 = (const float*)d_in[9],  *be2 = (const float*)d_in[10];
    const float* Wm1 = (const float*)d_in[11], *bm1 = (const float*)d_in[12];
    const float* Wm2 = (const float*)d_in[13], *bm2 = (const float*)d_in[14];
    const float* Wu1 = (const float*)d_in[15], *bu1 = (const float*)d_in[16];
    const float* Wu2 = (const float*)d_in[17], *bu2 = (const float*)d_in[18];
    const float* Wd1 = (const float*)d_in[19], *bd1 = (const float*)d_in[20];
    const float* Wd2 = (const float*)d_in[21], *bd2 = (const float*)d_in[22];
    float* out = (float*)d_out;

    cudaFuncSetAttribute(k_fuse, cudaFuncAttributeMaxDynamicSharedMemorySize, SMEM_FUSE);
    cudaFuncSetAttribute(k_node, cudaFuncAttributeMaxDynamicSharedMemorySize, SMEM_ND);

    const int* src = eix;
    const int* tgt = eix + NE;

    k_init<<<(NN * 8 + 255) / 256, 256>>>(h0);
    k_deg<<<(NE + 255) / 256, 256>>>(src, tgt);
    k_alloc<<<(NN + 255) / 256, 256>>>();
    k_fill<<<(NE + 255) / 256, 256>>>(src, tgt, ef);
    k_wprep<<<(20800 + 255) / 256, 256>>>(We2, be2, Wm1, bm1, Wm2, bm2,
                                          Wu1, bu1, Wu2, bu2, Wd1, bd1);

    for (int s = 0; s < 4; s++) {
        int step = s * 4;
        k_qp1<<<592, 256>>>(We1, be1, runoff, elev, step);
        k_edge1<<<6250, 256>>>(We1);
        k_fuse<<<FUSE_GRID, 256, SMEM_FUSE>>>();
        k_edge2<<<6250, 256>>>();
        k_node<<<444, 256, SMEM_ND>>>(elev, gl, Wd2, bd2, out, s);
    }
}

// round 15
// speedup vs baseline: 1.0463x; 1.0463x over previous
#include <cuda_runtime.h>
#include <cstdint>

#define NN 100000
#define NE 800000
typedef unsigned long long u64;

// ---------------- device scratch ----------------
__device__ __align__(16) float  g_hcur[NN * 8];
__device__ __align__(16) float g_qp[(size_t)NN * 128];  // Q1|Q2 (then P1|P2)
__device__ __align__(16) float g_u3[(size_t)NN * 64];   // cx@Wu1_top + bu1
__device__ __align__(16) float g_hsum[(size_t)NN * 64]; // Hsum1 then Hsum2
// CSR structures (built once per call; bucket order across nodes arbitrary)
__device__ int g_deg_src[NN], g_deg_tgt[NN];
__device__ int g_offs_src[NN], g_offs_tgt[NN];
__device__ int g_cur_src[NN], g_cur_tgt[NN];
__device__ int g_ctr[2];
__device__ float4 g_csr_src[NE];   // (tgt as int bits, ef0, ef1, ef2)
__device__ int    g_csr_tgt[NE];   // src
// folded weights
__device__ float g_wbig[64 * 192]; // We2 @ [Wm1_top | Wm1_bot | Wu1_top]
__device__ float g_bvec[192];      // be2 @ same
__device__ float g_cvec[192];      // [bm1 | 0 | bu1]
__device__ float g_w2u[4096];      // Wm2 @ Wu1[64:128]
__device__ float g_vb[64];         // bm2 @ Wu1[64:128]
__device__ float g_wud[4096];      // Wu2 @ Wd1
__device__ float g_bud[64];        // bu2 @ Wd1 + bd1

// ---------------- f32x2 helpers ----------------
__device__ __forceinline__ u64 pk2(float x) {
    u64 d; asm("mov.b64 %0, {%1, %1};" : "=l"(d) : "f"(x)); return d;
}
__device__ __forceinline__ u64 f2(u64 a, u64 b, u64 c) {
    u64 d; asm("fma.rn.f32x2 %0, %1, %2, %3;" : "=l"(d) : "l"(a), "l"(b), "l"(c)); return d;
}
__device__ __forceinline__ float2 up2(u64 a) {
    float2 r; asm("mov.b64 {%0, %1}, %2;" : "=f"(r.x), "=f"(r.y) : "l"(a)); return r;
}

// C[64 x cols] += A^T B ; A k-major As[k*AP+row], B Bs[k*BP+col]
template<int K, int AP, int BP>
__device__ __forceinline__ void mmacc(const float* As, const float* Bs,
                                      u64 acc[4][2], int e4, int c4) {
#pragma unroll 8
    for (int k = 0; k < K; k++) {
        float4 a = *(const float4*)(As + k * AP + e4);
        ulonglong2 b = *(const ulonglong2*)(Bs + k * BP + c4);
        u64 a0 = pk2(a.x), a1 = pk2(a.y), a2 = pk2(a.z), a3 = pk2(a.w);
        acc[0][0] = f2(a0, b.x, acc[0][0]); acc[0][1] = f2(a0, b.y, acc[0][1]);
        acc[1][0] = f2(a1, b.x, acc[1][0]); acc[1][1] = f2(a1, b.y, acc[1][1]);
        acc[2][0] = f2(a2, b.x, acc[2][0]); acc[2][1] = f2(a2, b.y, acc[2][1]);
        acc[3][0] = f2(a3, b.x, acc[3][0]); acc[3][1] = f2(a3, b.y, acc[3][1]);
    }
}

// ---------------- setup kernels ----------------
__global__ void k_init(const float* __restrict__ h0) {
    int i = blockIdx.x * blockDim.x + threadIdx.x;
    if (i < NN * 8) g_hcur[i] = h0[i];
    if (i < NN) { g_deg_src[i] = 0; g_deg_tgt[i] = 0; }
    if (i == 0) { g_ctr[0] = 0; g_ctr[1] = 0; }
}
__global__ void k_deg(const int* __restrict__ src, const int* __restrict__ tgt) {
    int e = blockIdx.x * blockDim.x + threadIdx.x;
    if (e < NE) {
        atomicAdd(&g_deg_src[src[e]], 1);
        atomicAdd(&g_deg_tgt[tgt[e]], 1);
    }
}
__global__ void k_alloc() {
    int n = blockIdx.x * blockDim.x + threadIdx.x;
    if (n < NN) {
        int o0 = atomicAdd(&g_ctr[0], g_deg_src[n]);
        g_offs_src[n] = o0; g_cur_src[n] = o0;
        int o1 = atomicAdd(&g_ctr[1], g_deg_tgt[n]);
        g_offs_tgt[n] = o1; g_cur_tgt[n] = o1;
    }
}
__global__ void k_fill(const int* __restrict__ src, const int* __restrict__ tgt,
                       const float* __restrict__ ef) {
    int e = blockIdx.x * blockDim.x + threadIdx.x;
    if (e >= NE) return;
    int s = src[e], t = tgt[e];
    float f0 = ef[(size_t)e * 3], f1 = ef[(size_t)e * 3 + 1], f2v = ef[(size_t)e * 3 + 2];
    int p = atomicAdd(&g_cur_src[s], 1);
    g_csr_src[p] = make_float4(__int_as_float(t), f0, f1, f2v);
    int q = atomicAdd(&g_cur_tgt[t], 1);
    g_csr_tgt[q] = s;
}
// weight folding
__global__ void k_wprep(const float* __restrict__ We2, const float* __restrict__ be2,
                        const float* __restrict__ Wm1, const float* __restrict__ bm1,
                        const float* __restrict__ Wm2, const float* __restrict__ bm2,
                        const float* __restrict__ Wu1, const float* __restrict__ bu1,
                        const float* __restrict__ Wu2, const float* __restrict__ bu2,
                        const float* __restrict__ Wd1, const float* __restrict__ bd1) {
    int idx = blockIdx.x * blockDim.x + threadIdx.x;
    if (idx < 12288) {
        int g = idx >> 12, rem = idx & 4095;
        int r = rem >> 6, c = rem & 63;
        const float* W = (g == 0) ? Wm1 : (g == 1) ? (Wm1 + 64 * 64) : Wu1;
        float s = 0.f;
#pragma unroll 8
        for (int b = 0; b < 64; b++) s += We2[r * 64 + b] * W[b * 64 + c];
        g_wbig[r * 192 + g * 64 + c] = s;
    } else if (idx < 12480) {
        int j = idx - 12288;
        int g = j >> 6, c = j & 63;
        const float* W = (g == 0) ? Wm1 : (g == 1) ? (Wm1 + 64 * 64) : Wu1;
        float s = 0.f;
#pragma unroll 8
        for (int b = 0; b < 64; b++) s += be2[b] * W[b * 64 + c];
        g_bvec[j] = s;
        g_cvec[j] = (g == 0) ? bm1[c] : (g == 2) ? bu1[c] : 0.f;
    } else if (idx < 16576) {
        int k = idx - 12480;
        int a = k >> 6, c = k & 63;
        float s = 0.f;
#pragma unroll 8
        for (int b = 0; b < 64; b++) s += Wm2[a * 64 + b] * Wu1[(64 + b) * 64 + c];
        g_w2u[k] = s;
    } else if (idx < 16640) {
        int c = idx - 16576;
        float s = 0.f;
#pragma unroll 8
        for (int b = 0; b < 64; b++) s += bm2[b] * Wu1[(64 + b) * 64 + c];
        g_vb[c] = s;
    } else if (idx < 20736) {
        int k = idx - 16640;
        int a = k >> 6, c = k & 63;
        float s = 0.f;
#pragma unroll 8
        for (int b = 0; b < 64; b++) s += Wu2[a * 64 + b] * Wd1[b * 64 + c];
        g_wud[k] = s;
    } else if (idx < 20800) {
        int c = idx - 20736;
        float s = bd1[c];
#pragma unroll 8
        for (int b = 0; b < 64; b++) s += bu2[b] * Wd1[b * 64 + c];
        g_bud[c] = s;
    }
}

// ------------- Q1 = nf@We1[3:24]+be1, Q2 = nf@We1[24:45]; nf built inline -------------
__global__ void __launch_bounds__(256) k_qp1(const float* __restrict__ We1,
                                             const float* __restrict__ be1,
                                             const float* __restrict__ runoff,
                                             const float* __restrict__ elev,
                                             int step) {
    __shared__ float Wq[24 * 128];
    __shared__ float A[24 * 64];
    __shared__ float b1s[64];
    const int tid = threadIdx.x;
    const int tx = tid & 15, ty = tid >> 4;
    const int c4 = tx * 4, e4 = ty * 4;

    for (int i = tid; i < 24 * 128; i += 256) {
        int r = i >> 7, c = i & 127;
        float v = 0.f;
        if (r < 21) v = (c < 64) ? We1[(3 + r) * 64 + c] : We1[(24 + r) * 64 + (c - 64)];
        Wq[i] = v;
    }
    if (tid < 64) b1s[tid] = be1[tid];

    const int ntiles = (NN + 63) / 64;
    for (int tile = blockIdx.x; tile < ntiles; tile += gridDim.x) {
        int n0 = tile * 64;
        __syncthreads();
        for (int i = tid; i < 384; i += 256) {
            int e = i & 63, q = i >> 6;
            int n = min(n0 + e, NN - 1);
            float4 v;
            if (q < 2)      v = *(const float4*)(g_hcur + n * 8 + q * 4);
            else if (q < 5) v = *(const float4*)(runoff + (size_t)n * 24 + step + (q - 2) * 4);
            else            v = make_float4(elev[n], 0.f, 0.f, 0.f);
            A[(q * 4 + 0) * 64 + e] = v.x; A[(q * 4 + 1) * 64 + e] = v.y;
            A[(q * 4 + 2) * 64 + e] = v.z; A[(q * 4 + 3) * 64 + e] = v.w;
        }
        __syncthreads();
        u64 acc0[4][2] = {}, acc1[4][2] = {};
        mmacc<24, 64, 128>(A, Wq, acc0, e4, c4);
        mmacc<24, 64, 128>(A, Wq + 64, acc1, e4, c4);
        float4 bb = *(const float4*)&b1s[c4];
#pragma unroll
        for (int i = 0; i < 4; i++) {
            int n = n0 + e4 + i;
            if (n < NN) {
                float2 p0 = up2(acc0[i][0]), p1 = up2(acc0[i][1]);
                *(float4*)(g_qp + (size_t)n * 128 + c4) =
                    make_float4(p0.x + bb.x, p0.y + bb.y, p1.x + bb.z, p1.y + bb.w);
                float2 r0 = up2(acc1[i][0]), r1 = up2(acc1[i][1]);
                *(float4*)(g_qp + (size_t)n * 128 + 64 + c4) =
                    make_float4(r0.x, r0.y, r1.x, r1.y);
            }
        }
    }
}

// ------------- edge pass 1 (4-way unrolled): Hsum1[n] = sum relu(Q1[n]+Q2[t]+ef@Wef) ------
__global__ void __launch_bounds__(256) k_edge1(const float* __restrict__ We1) {
    const int l = threadIdx.x & 15;
    const int gstride = gridDim.x * (blockDim.x >> 4);
    int n = blockIdx.x * (blockDim.x >> 4) + (threadIdx.x >> 4);
    const int c4 = l * 4;
    const float4 w0 = *(const float4*)(We1 + c4);
    const float4 w1 = *(const float4*)(We1 + 64 + c4);
    const float4 w2 = *(const float4*)(We1 + 128 + c4);
    const float4* __restrict__ gq = (const float4*)g_qp;

    for (; n < NN; n += gstride) {
        float4 q1 = gq[(size_t)n * 32 + l];
        int off = g_offs_src[n], end = off + g_deg_src[n];
        float4 acc = make_float4(0.f, 0.f, 0.f, 0.f);
        int i = off;
        for (; i + 4 <= end; i += 4) {
            float4 t0 = g_csr_src[i];
            float4 t1 = g_csr_src[i + 1];
            float4 t2 = g_csr_src[i + 2];
            float4 t3 = g_csr_src[i + 3];
            float4 a0 = gq[(size_t)__float_as_int(t0.x) * 32 + 16 + l];
            float4 a1 = gq[(size_t)__float_as_int(t1.x) * 32 + 16 + l];
            float4 a2 = gq[(size_t)__float_as_int(t2.x) * 32 + 16 + l];
            float4 a3 = gq[(size_t)__float_as_int(t3.x) * 32 + 16 + l];
            acc.x += fmaxf(q1.x + a0.x + t0.y * w0.x + t0.z * w1.x + t0.w * w2.x, 0.f);
            acc.y += fmaxf(q1.y + a0.y + t0.y * w0.y + t0.z * w1.y + t0.w * w2.y, 0.f);
            acc.z += fmaxf(q1.z + a0.z + t0.y * w0.z + t0.z * w1.z + t0.w * w2.z, 0.f);
            acc.w += fmaxf(q1.w + a0.w + t0.y * w0.w + t0.z * w1.w + t0.w * w2.w, 0.f);
            acc.x += fmaxf(q1.x + a1.x + t1.y * w0.x + t1.z * w1.x + t1.w * w2.x, 0.f);
            acc.y += fmaxf(q1.y + a1.y + t1.y * w0.y + t1.z * w1.y + t1.w * w2.y, 0.f);
            acc.z += fmaxf(q1.z + a1.z + t1.y * w0.z + t1.z * w1.z + t1.w * w2.z, 0.f);
            acc.w += fmaxf(q1.w + a1.w + t1.y * w0.w + t1.z * w1.w + t1.w * w2.w, 0.f);
            acc.x += fmaxf(q1.x + a2.x + t2.y * w0.x + t2.z * w1.x + t2.w * w2.x, 0.f);
            acc.y += fmaxf(q1.y + a2.y + t2.y * w0.y + t2.z * w1.y + t2.w * w2.y, 0.f);
            acc.z += fmaxf(q1.z + a2.z + t2.y * w0.z + t2.z * w1.z + t2.w * w2.z, 0.f);
            acc.w += fmaxf(q1.w + a2.w + t2.y * w0.w + t2.z * w1.w + t2.w * w2.w, 0.f);
            acc.x += fmaxf(q1.x + a3.x + t3.y * w0.x + t3.z * w1.x + t3.w * w2.x, 0.f);
            acc.y += fmaxf(q1.y + a3.y + t3.y * w0.y + t3.z * w1.y + t3.w * w2.y, 0.f);
            acc.z += fmaxf(q1.z + a3.z + t3.y * w0.z + t3.z * w1.z + t3.w * w2.z, 0.f);
            acc.w += fmaxf(q1.w + a3.w + t3.y * w0.w + t3.z * w1.w + t3.w * w2.w, 0.f);
        }
        for (; i < end; i++) {
            float4 te = g_csr_src[i];
            float4 q2 = gq[(size_t)__float_as_int(te.x) * 32 + 16 + l];
            acc.x += fmaxf(q1.x + q2.x + te.y * w0.x + te.z * w1.x + te.w * w2.x, 0.f);
            acc.y += fmaxf(q1.y + q2.y + te.y * w0.y + te.z * w1.y + te.w * w2.y, 0.f);
            acc.z += fmaxf(q1.z + q2.z + te.y * w0.z + te.z * w1.z + te.w * w2.z, 0.f);
            acc.w += fmaxf(q1.w + q2.w + te.y * w0.w + te.z * w1.w + te.w * w2.w, 0.f);
        }
        *(float4*)(g_hsum + (size_t)n * 64 + c4) = acc;
    }
}

// ------------- fused: [P1|P2|U3] = Hsum1 @ wbig + deg_src*bvec + cvec -------------
#define SMEM_FUSE ((12288 + 4352 + 192 + 192) * 4)
__global__ void __launch_bounds__(256) k_fuse() {
    extern __shared__ __align__(16) float sm[];
    float* Wb  = sm;            // 64x192
    float* A   = sm + 12288;    // 64x68
    float* bvs = sm + 16640;
    float* cvs = sm + 16832;

    const int tid = threadIdx.x;
    const int tx = tid & 15, ty = tid >> 4;
    const int c4 = tx * 4, e4 = ty * 4;

    for (int i = tid; i < 12288; i += 256) Wb[i] = g_wbig[i];
    if (tid < 192) { bvs[tid] = g_bvec[tid]; cvs[tid] = g_cvec[tid]; }

    const int ntiles = (NN + 63) / 64;
    for (int tile = blockIdx.x; tile < ntiles; tile += gridDim.x) {
        int n0 = tile * 64;
        __syncthreads();
        for (int i = tid; i < 1024; i += 256) {
            int e = i & 63, q = i >> 6;
            int n = min(n0 + e, NN - 1);
            float4 v = *(const float4*)(g_hsum + (size_t)n * 64 + q * 4);
            A[(q * 4 + 0) * 68 + e] = v.x; A[(q * 4 + 1) * 68 + e] = v.y;
            A[(q * 4 + 2) * 68 + e] = v.z; A[(q * 4 + 3) * 68 + e] = v.w;
        }
        __syncthreads();
        float degf[4];
#pragma unroll
        for (int i = 0; i < 4; i++) degf[i] = (float)g_deg_src[min(n0 + e4 + i, NN - 1)];
#pragma unroll
        for (int g = 0; g < 3; g++) {
            u64 acc[4][2] = {};
            mmacc<64, 68, 192>(A, Wb + g * 64, acc, e4, c4);
            float4 bv = *(const float4*)&bvs[g * 64 + c4];
            float4 cv = *(const float4*)&cvs[g * 64 + c4];
#pragma unroll
            for (int i = 0; i < 4; i++) {
                int n = n0 + e4 + i;
                if (n < NN) {
                    float2 p0 = up2(acc[i][0]), p1 = up2(acc[i][1]);
                    float4 o = make_float4(p0.x + degf[i] * bv.x + cv.x,
                                           p0.y + degf[i] * bv.y + cv.y,
                                           p1.x + degf[i] * bv.z + cv.z,
                                           p1.y + degf[i] * bv.w + cv.w);
                    if (g == 0)      *(float4*)(g_qp + (size_t)n * 128 + c4) = o;
                    else if (g == 1) *(float4*)(g_qp + (size_t)n * 128 + 64 + c4) = o;
                    else             *(float4*)(g_u3 + (size_t)n * 64 + c4) = o;
                }
            }
        }
    }
}

// ------------- edge pass 2 (4-way unrolled): Hsum2[n] = sum relu(P1[s]+P2[n]) -------------
__global__ void __launch_bounds__(256) k_edge2() {
    const int l = threadIdx.x & 15;
    const int gstride = gridDim.x * (blockDim.x >> 4);
    int n = blockIdx.x * (blockDim.x >> 4) + (threadIdx.x >> 4);
    const float4* __restrict__ gq = (const float4*)g_qp;

    for (; n < NN; n += gstride) {
        float4 p2 = gq[(size_t)n * 32 + 16 + l];
        int off = g_offs_tgt[n], end = off + g_deg_tgt[n];
        float4 acc = make_float4(0.f, 0.f, 0.f, 0.f);
        int i = off;
        for (; i + 4 <= end; i += 4) {
            int s0 = g_csr_tgt[i];
            int s1 = g_csr_tgt[i + 1];
            int s2 = g_csr_tgt[i + 2];
            int s3 = g_csr_tgt[i + 3];
            float4 a0 = gq[(size_t)s0 * 32 + l];
            float4 a1 = gq[(size_t)s1 * 32 + l];
            float4 a2 = gq[(size_t)s2 * 32 + l];
            float4 a3 = gq[(size_t)s3 * 32 + l];
            acc.x += fmaxf(a0.x + p2.x, 0.f) + fmaxf(a1.x + p2.x, 0.f)
                   + fmaxf(a2.x + p2.x, 0.f) + fmaxf(a3.x + p2.x, 0.f);
            acc.y += fmaxf(a0.y + p2.y, 0.f) + fmaxf(a1.y + p2.y, 0.f)
                   + fmaxf(a2.y + p2.y, 0.f) + fmaxf(a3.y + p2.y, 0.f);
            acc.z += fmaxf(a0.z + p2.z, 0.f) + fmaxf(a1.z + p2.z, 0.f)
                   + fmaxf(a2.z + p2.z, 0.f) + fmaxf(a3.z + p2.z, 0.f);
            acc.w += fmaxf(a0.w + p2.w, 0.f) + fmaxf(a1.w + p2.w, 0.f)
                   + fmaxf(a2.w + p2.w, 0.f) + fmaxf(a3.w + p2.w, 0.f);
        }
        for (; i < end; i++) {
            int s = g_csr_tgt[i];
            float4 p1 = gq[(size_t)s * 32 + l];
            acc.x += fmaxf(p1.x + p2.x, 0.f);
            acc.y += fmaxf(p1.y + p2.y, 0.f);
            acc.z += fmaxf(p1.z + p2.z, 0.f);
            acc.w += fmaxf(p1.w + p2.w, 0.f);
        }
        *(float4*)(g_hsum + (size_t)n * 64 + l * 4) = acc;
    }
}

// ---------------- node: 2 GEMMs (w2u, wud) + decoder + head ----------------
#define SMEM_ND (17296 * 4)
__global__ void __launch_bounds__(256) k_node(
    const float* __restrict__ elev, const float* __restrict__ gl,
    const float* __restrict__ Wd2, const float* __restrict__ bd2,
    float* __restrict__ out, int sidx)
{
    extern __shared__ __align__(16) float sm[];
    float* W1   = sm;          float* W2  = sm + 4096;
    float* W4   = sm + 8192;
    float* vbs  = sm + 8448;   float* budv = sm + 8512;
    float* b4v  = sm + 8576;
    float* A    = sm + 8592;   float* Ps = A;
    float* Hs   = sm + 12944;

    const int tid = threadIdx.x;
    const int tx = tid & 15, ty = tid >> 4;
    const int c4 = tx * 4, e4 = ty * 4;

    for (int i = tid; i < 4096; i += 256) { W1[i] = g_w2u[i]; W2[i] = g_wud[i]; }
    if (tid < 256) W4[tid] = Wd2[tid];
    if (tid < 64) { vbs[tid] = g_vb[tid]; budv[tid] = g_bud[tid]; }
    if (tid < 4) b4v[tid] = bd2[tid];

    const int ntiles = (NN + 63) / 64;
    for (int tile = blockIdx.x; tile < ntiles; tile += gridDim.x) {
        int n0 = tile * 64;
        __syncthreads();
        for (int i = tid; i < 1024; i += 256) {
            int e = i & 63, q = i >> 6;
            int n = min(n0 + e, NN - 1);
            float4 v = *(const float4*)(g_hsum + (size_t)n * 64 + q * 4);
            A[(q * 4 + 0) * 68 + e] = v.x; A[(q * 4 + 1) * 68 + e] = v.y;
            A[(q * 4 + 2) * 68 + e] = v.z; A[(q * 4 + 3) * 68 + e] = v.w;
        }
        __syncthreads();
        u64 acc[4][2] = {};
        mmacc<64, 68, 64>(A, W1, acc, e4, c4);
        {
            float4 vv = *(const float4*)&vbs[c4];
            float hv[4][4];
#pragma unroll
            for (int i = 0; i < 4; i++) {
                int nc = min(n0 + e4 + i, NN - 1);
                float degf = (float)g_deg_tgt[nc];
                float4 u3 = *(const float4*)(g_u3 + (size_t)nc * 64 + c4);
                float2 p0 = up2(acc[i][0]), p1 = up2(acc[i][1]);
                hv[i][0] = fmaxf(p0.x + u3.x + degf * vv.x, 0.f);
                hv[i][1] = fmaxf(p0.y + u3.y + degf * vv.y, 0.f);
                hv[i][2] = fmaxf(p1.x + u3.z + degf * vv.z, 0.f);
                hv[i][3] = fmaxf(p1.y + u3.w + degf * vv.w, 0.f);
            }
            __syncthreads();
#pragma unroll
            for (int j = 0; j < 4; j++)
                *(float4*)&Hs[(c4 + j) * 68 + e4] = make_float4(hv[0][j], hv[1][j], hv[2][j], hv[3][j]);
        }
        __syncthreads();
        u64 acc2[4][2] = {};
        mmacc<64, 68, 64>(Hs, W2, acc2, e4, c4);
        {
            float4 bb = *(const float4*)&budv[c4];
            float pv[4][4];
#pragma unroll
            for (int i = 0; i < 4; i++) {
                float2 p0 = up2(acc2[i][0]), p1 = up2(acc2[i][1]);
                pv[i][0] = fmaxf(p0.x + bb.x, 0.f); pv[i][1] = fmaxf(p0.y + bb.y, 0.f);
                pv[i][2] = fmaxf(p1.x + bb.z, 0.f); pv[i][3] = fmaxf(p1.y + bb.w, 0.f);
            }
            __syncthreads();
#pragma unroll
            for (int j = 0; j < 4; j++)
                *(float4*)&Ps[(c4 + j) * 68 + e4] = make_float4(pv[0][j], pv[1][j], pv[2][j], pv[3][j]);
        }
        __syncthreads();
        // decoder 64->4 + head
        int node = tid >> 2, c = tid & 3;
        float dec = b4v[c];
#pragma unroll 8
        for (int k = 0; k < 64; k++) dec += Ps[k * 68 + node] * W4[k * 4 + c];

        int n = n0 + node;
        int nc = min(n, NN - 1);
        float ev  = elev[nc];
        float g   = gl[nc];
        float h7  = g_hcur[nc * 8 + 7];
        float old = g_hcur[nc * 8 + 4 + c];
        __syncwarp();
        if (n < NN) {
            float ph = 0.5f * dec + 0.5f * (h7 - ev) + ev;
            float pc = fminf(ph, g);
            float pl = fmaxf(pc, ev);
            out[(size_t)n * 16 + sidx * 4 + c] = pl;
            g_hcur[n * 8 + c]     = old;
            g_hcur[n * 8 + 4 + c] = pc;
        }
    }
}

// ---------------- launch ----------------
extern "C" void kernel_launch(void* const* d_in, const int* in_sizes, int n_in,
                              void* d_out, int out_size) {
    const float* h0     = (const float*)d_in[0];
    const float* runoff = (const float*)d_in[1];
    const float* elev   = (const float*)d_in[2];
    const float* gl     = (const float*)d_in[3];
    const float* ef     = (const float*)d_in[4];
    const int*   eix    = (const int*)d_in[5];
    const float* We1 = (const float*)d_in[7],  *be1 = (const float*)d_in[8];
    const float* We2 = (const float*)d_in[9],  *be2 = (const float*)d_in[10];
    const float* Wm1 = (const float*)d_in[11], *bm1 = (const float*)d_in[12];
    const float* Wm2 = (const float*)d_in[13], *bm2 = (const float*)d_in[14];
    const float* Wu1 = (const float*)d_in[15], *bu1 = (const float*)d_in[16];
    const float* Wu2 = (const float*)d_in[17], *bu2 = (const float*)d_in[18];
    const float* Wd1 = (const float*)d_in[19], *bd1 = (const float*)d_in[20];
    const float* Wd2 = (const float*)d_in[21], *bd2 = (const float*)d_in[22];
    float* out = (float*)d_out;

    cudaFuncSetAttribute(k_fuse, cudaFuncAttributeMaxDynamicSharedMemorySize, SMEM_FUSE);
    cudaFuncSetAttribute(k_node, cudaFuncAttributeMaxDynamicSharedMemorySize, SMEM_ND);

    const int* src = eix;
    const int* tgt = eix + NE;

    k_init<<<(NN * 8 + 255) / 256, 256>>>(h0);
    k_deg<<<(NE + 255) / 256, 256>>>(src, tgt);
    k_alloc<<<(NN + 255) / 256, 256>>>();
    k_fill<<<(NE + 255) / 256, 256>>>(src, tgt, ef);
    k_wprep<<<(20800 + 255) / 256, 256>>>(We2, be2, Wm1, bm1, Wm2, bm2,
                                          Wu1, bu1, Wu2, bu2, Wd1, bd1);

    for (int s = 0; s < 4; s++) {
        int step = s * 4;
        k_qp1<<<592, 256>>>(We1, be1, runoff, elev, step);
        k_edge1<<<6250, 256>>>(We1);
        k_fuse<<<444, 256, SMEM_FUSE>>>();
        k_edge2<<<6250, 256>>>();
        k_node<<<444, 256, SMEM_ND>>>(elev, gl, Wd2, bd2, out, s);
    }
}

// round 16
// speedup vs baseline: 1.0847x; 1.0367x over previous
#include <cuda_runtime.h>
#include <cstdint>

#define NN 100000
#define NE 800000
typedef unsigned long long u64;

// ---------------- device scratch ----------------
__device__ __align__(16) float  g_hcur[NN * 8];
__device__ __align__(16) float g_qp[(size_t)NN * 128];  // Q1|Q2 (then P1|P2)
__device__ __align__(16) float g_u3[(size_t)NN * 64];   // cx@Wu1_top + bu1
__device__ __align__(16) float g_hsum[(size_t)NN * 64]; // Hsum1 then Hsum2
// CSR structures (built once per call; bucket order across nodes arbitrary)
__device__ int g_deg_src[NN], g_deg_tgt[NN];
__device__ int g_offs_src[NN], g_offs_tgt[NN];
__device__ int g_cur_src[NN], g_cur_tgt[NN];
__device__ int g_ctr[2];
__device__ float4 g_csr_src[NE];   // (tgt as int bits, ef0, ef1, ef2)
__device__ int    g_csr_tgt[NE];   // src
// folded weights
__device__ float g_wbig[64 * 192]; // We2 @ [Wm1_top | Wm1_bot | Wu1_top]
__device__ float g_bvec[192];      // be2 @ same
__device__ float g_cvec[192];      // [bm1 | 0 | bu1]
__device__ float g_w2u[4096];      // Wm2 @ Wu1[64:128]
__device__ float g_vb[64];         // bm2 @ Wu1[64:128]
__device__ float g_wud[4096];      // Wu2 @ Wd1
__device__ float g_bud[64];        // bu2 @ Wd1 + bd1

// ---------------- f32x2 helpers ----------------
__device__ __forceinline__ u64 pk2(float x) {
    u64 d; asm("mov.b64 %0, {%1, %1};" : "=l"(d) : "f"(x)); return d;
}
__device__ __forceinline__ u64 f2(u64 a, u64 b, u64 c) {
    u64 d; asm("fma.rn.f32x2 %0, %1, %2, %3;" : "=l"(d) : "l"(a), "l"(b), "l"(c)); return d;
}
__device__ __forceinline__ float2 up2(u64 a) {
    float2 r; asm("mov.b64 {%0, %1}, %2;" : "=f"(r.x), "=f"(r.y) : "l"(a)); return r;
}

// C[64 x cols] += A^T B ; A k-major As[k*AP+row], B Bs[k*BP+col]
template<int K, int AP, int BP>
__device__ __forceinline__ void mmacc(const float* As, const float* Bs,
                                      u64 acc[4][2], int e4, int c4) {
#pragma unroll 8
    for (int k = 0; k < K; k++) {
        float4 a = *(const float4*)(As + k * AP + e4);
        ulonglong2 b = *(const ulonglong2*)(Bs + k * BP + c4);
        u64 a0 = pk2(a.x), a1 = pk2(a.y), a2 = pk2(a.z), a3 = pk2(a.w);
        acc[0][0] = f2(a0, b.x, acc[0][0]); acc[0][1] = f2(a0, b.y, acc[0][1]);
        acc[1][0] = f2(a1, b.x, acc[1][0]); acc[1][1] = f2(a1, b.y, acc[1][1]);
        acc[2][0] = f2(a2, b.x, acc[2][0]); acc[2][1] = f2(a2, b.y, acc[2][1]);
        acc[3][0] = f2(a3, b.x, acc[3][0]); acc[3][1] = f2(a3, b.y, acc[3][1]);
    }
}

// ---------------- setup kernels ----------------
// init h0 copy + zero degrees + count degrees, all in one launch (NN*8 >= NE)
__global__ void k_init(const float* __restrict__ h0,
                       const int* __restrict__ src, const int* __restrict__ tgt) {
    int i = blockIdx.x * blockDim.x + threadIdx.x;
    if (i < NN) { g_deg_src[i] = 0; g_deg_tgt[i] = 0; }
    if (i == 0) { g_ctr[0] = 0; g_ctr[1] = 0; }
    if (i < NN * 8) g_hcur[i] = h0[i];
}
__global__ void k_deg(const int* __restrict__ src, const int* __restrict__ tgt) {
    int e = blockIdx.x * blockDim.x + threadIdx.x;
    if (e < NE) {
        atomicAdd(&g_deg_src[src[e]], 1);
        atomicAdd(&g_deg_tgt[tgt[e]], 1);
    }
}
// bump-alloc CSR ranges + fold weights, one launch (independent index ranges)
__global__ void k_allocprep(const float* __restrict__ We2, const float* __restrict__ be2,
                            const float* __restrict__ Wm1, const float* __restrict__ bm1,
                            const float* __restrict__ Wm2, const float* __restrict__ bm2,
                            const float* __restrict__ Wu1, const float* __restrict__ bu1,
                            const float* __restrict__ Wu2, const float* __restrict__ bu2,
                            const float* __restrict__ Wd1, const float* __restrict__ bd1) {
    int idx = blockIdx.x * blockDim.x + threadIdx.x;
    // CSR range allocation for all nodes
    if (idx >= 20800 && idx < 20800 + NN) {
        int n = idx - 20800;
        int o0 = atomicAdd(&g_ctr[0], g_deg_src[n]);
        g_offs_src[n] = o0; g_cur_src[n] = o0;
        int o1 = atomicAdd(&g_ctr[1], g_deg_tgt[n]);
        g_offs_tgt[n] = o1; g_cur_tgt[n] = o1;
        return;
    }
    if (idx < 12288) {
        int g = idx >> 12, rem = idx & 4095;
        int r = rem >> 6, c = rem & 63;
        const float* W = (g == 0) ? Wm1 : (g == 1) ? (Wm1 + 64 * 64) : Wu1;
        float s = 0.f;
#pragma unroll 8
        for (int b = 0; b < 64; b++) s += We2[r * 64 + b] * W[b * 64 + c];
        g_wbig[r * 192 + g * 64 + c] = s;
    } else if (idx < 12480) {
        int j = idx - 12288;
        int g = j >> 6, c = j & 63;
        const float* W = (g == 0) ? Wm1 : (g == 1) ? (Wm1 + 64 * 64) : Wu1;
        float s = 0.f;
#pragma unroll 8
        for (int b = 0; b < 64; b++) s += be2[b] * W[b * 64 + c];
        g_bvec[j] = s;
        g_cvec[j] = (g == 0) ? bm1[c] : (g == 2) ? bu1[c] : 0.f;
    } else if (idx < 16576) {
        int k = idx - 12480;
        int a = k >> 6, c = k & 63;
        float s = 0.f;
#pragma unroll 8
        for (int b = 0; b < 64; b++) s += Wm2[a * 64 + b] * Wu1[(64 + b) * 64 + c];
        g_w2u[k] = s;
    } else if (idx < 16640) {
        int c = idx - 16576;
        float s = 0.f;
#pragma unroll 8
        for (int b = 0; b < 64; b++) s += bm2[b] * Wu1[(64 + b) * 64 + c];
        g_vb[c] = s;
    } else if (idx < 20736) {
        int k = idx - 16640;
        int a = k >> 6, c = k & 63;
        float s = 0.f;
#pragma unroll 8
        for (int b = 0; b < 64; b++) s += Wu2[a * 64 + b] * Wd1[b * 64 + c];
        g_wud[k] = s;
    } else if (idx < 20800) {
        int c = idx - 20736;
        float s = bd1[c];
#pragma unroll 8
        for (int b = 0; b < 64; b++) s += bu2[b] * Wd1[b * 64 + c];
        g_bud[c] = s;
    }
}
__global__ void k_fill(const int* __restrict__ src, const int* __restrict__ tgt,
                       const float* __restrict__ ef) {
    int e = blockIdx.x * blockDim.x + threadIdx.x;
    if (e >= NE) return;
    int s = src[e], t = tgt[e];
    float f0 = ef[(size_t)e * 3], f1 = ef[(size_t)e * 3 + 1], f2v = ef[(size_t)e * 3 + 2];
    int p = atomicAdd(&g_cur_src[s], 1);
    g_csr_src[p] = make_float4(__int_as_float(t), f0, f1, f2v);
    int q = atomicAdd(&g_cur_tgt[t], 1);
    g_csr_tgt[q] = s;
}

// ------------- Q1 = nf@We1[3:24]+be1, Q2 = nf@We1[24:45]; nf built inline -------------
__global__ void __launch_bounds__(256) k_qp1(const float* __restrict__ We1,
                                             const float* __restrict__ be1,
                                             const float* __restrict__ runoff,
                                             const float* __restrict__ elev,
                                             int step) {
    __shared__ float Wq[24 * 128];
    __shared__ float A[24 * 64];
    __shared__ float b1s[64];
    const int tid = threadIdx.x;
    const int tx = tid & 15, ty = tid >> 4;
    const int c4 = tx * 4, e4 = ty * 4;

    for (int i = tid; i < 24 * 128; i += 256) {
        int r = i >> 7, c = i & 127;
        float v = 0.f;
        if (r < 21) v = (c < 64) ? We1[(3 + r) * 64 + c] : We1[(24 + r) * 64 + (c - 64)];
        Wq[i] = v;
    }
    if (tid < 64) b1s[tid] = be1[tid];

    const int ntiles = (NN + 63) / 64;
    for (int tile = blockIdx.x; tile < ntiles; tile += gridDim.x) {
        int n0 = tile * 64;
        __syncthreads();
        for (int i = tid; i < 384; i += 256) {
            int e = i & 63, q = i >> 6;
            int n = min(n0 + e, NN - 1);
            float4 v;
            if (q < 2)      v = *(const float4*)(g_hcur + n * 8 + q * 4);
            else if (q < 5) v = *(const float4*)(runoff + (size_t)n * 24 + step + (q - 2) * 4);
            else            v = make_float4(elev[n], 0.f, 0.f, 0.f);
            A[(q * 4 + 0) * 64 + e] = v.x; A[(q * 4 + 1) * 64 + e] = v.y;
            A[(q * 4 + 2) * 64 + e] = v.z; A[(q * 4 + 3) * 64 + e] = v.w;
        }
        __syncthreads();
        u64 acc0[4][2] = {}, acc1[4][2] = {};
        mmacc<24, 64, 128>(A, Wq, acc0, e4, c4);
        mmacc<24, 64, 128>(A, Wq + 64, acc1, e4, c4);
        float4 bb = *(const float4*)&b1s[c4];
#pragma unroll
        for (int i = 0; i < 4; i++) {
            int n = n0 + e4 + i;
            if (n < NN) {
                float2 p0 = up2(acc0[i][0]), p1 = up2(acc0[i][1]);
                *(float4*)(g_qp + (size_t)n * 128 + c4) =
                    make_float4(p0.x + bb.x, p0.y + bb.y, p1.x + bb.z, p1.y + bb.w);
                float2 r0 = up2(acc1[i][0]), r1 = up2(acc1[i][1]);
                *(float4*)(g_qp + (size_t)n * 128 + 64 + c4) =
                    make_float4(r0.x, r0.y, r1.x, r1.y);
            }
        }
    }
}

// ------------- edge pass 1 (4-way unrolled): Hsum1[n] = sum relu(Q1[n]+Q2[t]+ef@Wef) ------
__global__ void __launch_bounds__(256) k_edge1(const float* __restrict__ We1) {
    const int l = threadIdx.x & 15;
    const int gstride = gridDim.x * (blockDim.x >> 4);
    int n = blockIdx.x * (blockDim.x >> 4) + (threadIdx.x >> 4);
    const int c4 = l * 4;
    const float4 w0 = *(const float4*)(We1 + c4);
    const float4 w1 = *(const float4*)(We1 + 64 + c4);
    const float4 w2 = *(const float4*)(We1 + 128 + c4);
    const float4* __restrict__ gq = (const float4*)g_qp;

    for (; n < NN; n += gstride) {
        float4 q1 = gq[(size_t)n * 32 + l];
        int off = g_offs_src[n], end = off + g_deg_src[n];
        float4 acc = make_float4(0.f, 0.f, 0.f, 0.f);
        int i = off;
        for (; i + 4 <= end; i += 4) {
            float4 t0 = g_csr_src[i];
            float4 t1 = g_csr_src[i + 1];
            float4 t2 = g_csr_src[i + 2];
            float4 t3 = g_csr_src[i + 3];
            float4 a0 = gq[(size_t)__float_as_int(t0.x) * 32 + 16 + l];
            float4 a1 = gq[(size_t)__float_as_int(t1.x) * 32 + 16 + l];
            float4 a2 = gq[(size_t)__float_as_int(t2.x) * 32 + 16 + l];
            float4 a3 = gq[(size_t)__float_as_int(t3.x) * 32 + 16 + l];
            acc.x += fmaxf(q1.x + a0.x + t0.y * w0.x + t0.z * w1.x + t0.w * w2.x, 0.f);
            acc.y += fmaxf(q1.y + a0.y + t0.y * w0.y + t0.z * w1.y + t0.w * w2.y, 0.f);
            acc.z += fmaxf(q1.z + a0.z + t0.y * w0.z + t0.z * w1.z + t0.w * w2.z, 0.f);
            acc.w += fmaxf(q1.w + a0.w + t0.y * w0.w + t0.z * w1.w + t0.w * w2.w, 0.f);
            acc.x += fmaxf(q1.x + a1.x + t1.y * w0.x + t1.z * w1.x + t1.w * w2.x, 0.f);
            acc.y += fmaxf(q1.y + a1.y + t1.y * w0.y + t1.z * w1.y + t1.w * w2.y, 0.f);
            acc.z += fmaxf(q1.z + a1.z + t1.y * w0.z + t1.z * w1.z + t1.w * w2.z, 0.f);
            acc.w += fmaxf(q1.w + a1.w + t1.y * w0.w + t1.z * w1.w + t1.w * w2.w, 0.f);
            acc.x += fmaxf(q1.x + a2.x + t2.y * w0.x + t2.z * w1.x + t2.w * w2.x, 0.f);
            acc.y += fmaxf(q1.y + a2.y + t2.y * w0.y + t2.z * w1.y + t2.w * w2.y, 0.f);
            acc.z += fmaxf(q1.z + a2.z + t2.y * w0.z + t2.z * w1.z + t2.w * w2.z, 0.f);
            acc.w += fmaxf(q1.w + a2.w + t2.y * w0.w + t2.z * w1.w + t2.w * w2.w, 0.f);
            acc.x += fmaxf(q1.x + a3.x + t3.y * w0.x + t3.z * w1.x + t3.w * w2.x, 0.f);
            acc.y += fmaxf(q1.y + a3.y + t3.y * w0.y + t3.z * w1.y + t3.w * w2.y, 0.f);
            acc.z += fmaxf(q1.z + a3.z + t3.y * w0.z + t3.z * w1.z + t3.w * w2.z, 0.f);
            acc.w += fmaxf(q1.w + a3.w + t3.y * w0.w + t3.z * w1.w + t3.w * w2.w, 0.f);
        }
        for (; i < end; i++) {
            float4 te = g_csr_src[i];
            float4 q2 = gq[(size_t)__float_as_int(te.x) * 32 + 16 + l];
            acc.x += fmaxf(q1.x + q2.x + te.y * w0.x + te.z * w1.x + te.w * w2.x, 0.f);
            acc.y += fmaxf(q1.y + q2.y + te.y * w0.y + te.z * w1.y + te.w * w2.y, 0.f);
            acc.z += fmaxf(q1.z + q2.z + te.y * w0.z + te.z * w1.z + te.w * w2.z, 0.f);
            acc.w += fmaxf(q1.w + q2.w + te.y * w0.w + te.z * w1.w + te.w * w2.w, 0.f);
        }
        *(float4*)(g_hsum + (size_t)n * 64 + c4) = acc;
    }
}

// ------------- fused: [P1|P2|U3] = Hsum1 @ wbig + deg_src*bvec + cvec -------------
#define SMEM_FUSE ((12288 + 4352 + 192 + 192) * 4)
__global__ void __launch_bounds__(256) k_fuse() {
    extern __shared__ __align__(16) float sm[];
    float* Wb  = sm;            // 64x192
    float* A   = sm + 12288;    // 64x68
    float* bvs = sm + 16640;
    float* cvs = sm + 16832;

    const int tid = threadIdx.x;
    const int tx = tid & 15, ty = tid >> 4;
    const int c4 = tx * 4, e4 = ty * 4;

    for (int i = tid; i < 12288; i += 256) Wb[i] = g_wbig[i];
    if (tid < 192) { bvs[tid] = g_bvec[tid]; cvs[tid] = g_cvec[tid]; }

    const int ntiles = (NN + 63) / 64;
    for (int tile = blockIdx.x; tile < ntiles; tile += gridDim.x) {
        int n0 = tile * 64;
        __syncthreads();
        for (int i = tid; i < 1024; i += 256) {
            int e = i & 63, q = i >> 6;
            int n = min(n0 + e, NN - 1);
            float4 v = *(const float4*)(g_hsum + (size_t)n * 64 + q * 4);
            A[(q * 4 + 0) * 68 + e] = v.x; A[(q * 4 + 1) * 68 + e] = v.y;
            A[(q * 4 + 2) * 68 + e] = v.z; A[(q * 4 + 3) * 68 + e] = v.w;
        }
        __syncthreads();
        float degf[4];
#pragma unroll
        for (int i = 0; i < 4; i++) degf[i] = (float)g_deg_src[min(n0 + e4 + i, NN - 1)];
#pragma unroll
        for (int g = 0; g < 3; g++) {
            u64 acc[4][2] = {};
            mmacc<64, 68, 192>(A, Wb + g * 64, acc, e4, c4);
            float4 bv = *(const float4*)&bvs[g * 64 + c4];
            float4 cv = *(const float4*)&cvs[g * 64 + c4];
#pragma unroll
            for (int i = 0; i < 4; i++) {
                int n = n0 + e4 + i;
                if (n < NN) {
                    float2 p0 = up2(acc[i][0]), p1 = up2(acc[i][1]);
                    float4 o = make_float4(p0.x + degf[i] * bv.x + cv.x,
                                           p0.y + degf[i] * bv.y + cv.y,
                                           p1.x + degf[i] * bv.z + cv.z,
                                           p1.y + degf[i] * bv.w + cv.w);
                    if (g == 0)      *(float4*)(g_qp + (size_t)n * 128 + c4) = o;
                    else if (g == 1) *(float4*)(g_qp + (size_t)n * 128 + 64 + c4) = o;
                    else             *(float4*)(g_u3 + (size_t)n * 64 + c4) = o;
                }
            }
        }
    }
}

// ------------- edge pass 2 (4-way unrolled): Hsum2[n] = sum relu(P1[s]+P2[n]) -------------
__global__ void __launch_bounds__(256) k_edge2() {
    const int l = threadIdx.x & 15;
    const int gstride = gridDim.x * (blockDim.x >> 4);
    int n = blockIdx.x * (blockDim.x >> 4) + (threadIdx.x >> 4);
    const float4* __restrict__ gq = (const float4*)g_qp;

    for (; n < NN; n += gstride) {
        float4 p2 = gq[(size_t)n * 32 + 16 + l];
        int off = g_offs_tgt[n], end = off + g_deg_tgt[n];
        float4 acc = make_float4(0.f, 0.f, 0.f, 0.f);
        int i = off;
        for (; i + 4 <= end; i += 4) {
            int s0 = g_csr_tgt[i];
            int s1 = g_csr_tgt[i + 1];
            int s2 = g_csr_tgt[i + 2];
            int s3 = g_csr_tgt[i + 3];
            float4 a0 = gq[(size_t)s0 * 32 + l];
            float4 a1 = gq[(size_t)s1 * 32 + l];
            float4 a2 = gq[(size_t)s2 * 32 + l];
            float4 a3 = gq[(size_t)s3 * 32 + l];
            acc.x += fmaxf(a0.x + p2.x, 0.f) + fmaxf(a1.x + p2.x, 0.f)
                   + fmaxf(a2.x + p2.x, 0.f) + fmaxf(a3.x + p2.x, 0.f);
            acc.y += fmaxf(a0.y + p2.y, 0.f) + fmaxf(a1.y + p2.y, 0.f)
                   + fmaxf(a2.y + p2.y, 0.f) + fmaxf(a3.y + p2.y, 0.f);
            acc.z += fmaxf(a0.z + p2.z, 0.f) + fmaxf(a1.z + p2.z, 0.f)
                   + fmaxf(a2.z + p2.z, 0.f) + fmaxf(a3.z + p2.z, 0.f);
            acc.w += fmaxf(a0.w + p2.w, 0.f) + fmaxf(a1.w + p2.w, 0.f)
                   + fmaxf(a2.w + p2.w, 0.f) + fmaxf(a3.w + p2.w, 0.f);
        }
        for (; i < end; i++) {
            int s = g_csr_tgt[i];
            float4 p1 = gq[(size_t)s * 32 + l];
            acc.x += fmaxf(p1.x + p2.x, 0.f);
            acc.y += fmaxf(p1.y + p2.y, 0.f);
            acc.z += fmaxf(p1.z + p2.z, 0.f);
            acc.w += fmaxf(p1.w + p2.w, 0.f);
        }
        *(float4*)(g_hsum + (size_t)n * 64 + l * 4) = acc;
    }
}

// ---------------- node: 2 GEMMs (w2u, wud) + decoder + head ----------------
#define SMEM_ND (17296 * 4)
__global__ void __launch_bounds__(256) k_node(
    const float* __restrict__ elev, const float* __restrict__ gl,
    const float* __restrict__ Wd2, const float* __restrict__ bd2,
    float* __restrict__ out, int sidx)
{
    extern __shared__ __align__(16) float sm[];
    float* W1   = sm;          float* W2  = sm + 4096;
    float* W4   = sm + 8192;
    float* vbs  = sm + 8448;   float* budv = sm + 8512;
    float* b4v  = sm + 8576;
    float* A    = sm + 8592;   float* Ps = A;
    float* Hs   = sm + 12944;

    const int tid = threadIdx.x;
    const int tx = tid & 15, ty = tid >> 4;
    const int c4 = tx * 4, e4 = ty * 4;

    for (int i = tid; i < 4096; i += 256) { W1[i] = g_w2u[i]; W2[i] = g_wud[i]; }
    if (tid < 256) W4[tid] = Wd2[tid];
    if (tid < 64) { vbs[tid] = g_vb[tid]; budv[tid] = g_bud[tid]; }
    if (tid < 4) b4v[tid] = bd2[tid];

    const int ntiles = (NN + 63) / 64;
    for (int tile = blockIdx.x; tile < ntiles; tile += gridDim.x) {
        int n0 = tile * 64;
        __syncthreads();
        for (int i = tid; i < 1024; i += 256) {
            int e = i & 63, q = i >> 6;
            int n = min(n0 + e, NN - 1);
            float4 v = *(const float4*)(g_hsum + (size_t)n * 64 + q * 4);
            A[(q * 4 + 0) * 68 + e] = v.x; A[(q * 4 + 1) * 68 + e] = v.y;
            A[(q * 4 + 2) * 68 + e] = v.z; A[(q * 4 + 3) * 68 + e] = v.w;
        }
        __syncthreads();
        u64 acc[4][2] = {};
        mmacc<64, 68, 64>(A, W1, acc, e4, c4);
        {
            float4 vv = *(const float4*)&vbs[c4];
            float hv[4][4];
#pragma unroll
            for (int i = 0; i < 4; i++) {
                int nc = min(n0 + e4 + i, NN - 1);
                float degf = (float)g_deg_tgt[nc];
                float4 u3 = *(const float4*)(g_u3 + (size_t)nc * 64 + c4);
                float2 p0 = up2(acc[i][0]), p1 = up2(acc[i][1]);
                hv[i][0] = fmaxf(p0.x + u3.x + degf * vv.x, 0.f);
                hv[i][1] = fmaxf(p0.y + u3.y + degf * vv.y, 0.f);
                hv[i][2] = fmaxf(p1.x + u3.z + degf * vv.z, 0.f);
                hv[i][3] = fmaxf(p1.y + u3.w + degf * vv.w, 0.f);
            }
            __syncthreads();
#pragma unroll
            for (int j = 0; j < 4; j++)
                *(float4*)&Hs[(c4 + j) * 68 + e4] = make_float4(hv[0][j], hv[1][j], hv[2][j], hv[3][j]);
        }
        __syncthreads();
        u64 acc2[4][2] = {};
        mmacc<64, 68, 64>(Hs, W2, acc2, e4, c4);
        {
            float4 bb = *(const float4*)&budv[c4];
            float pv[4][4];
#pragma unroll
            for (int i = 0; i < 4; i++) {
                float2 p0 = up2(acc2[i][0]), p1 = up2(acc2[i][1]);
                pv[i][0] = fmaxf(p0.x + bb.x, 0.f); pv[i][1] = fmaxf(p0.y + bb.y, 0.f);
                pv[i][2] = fmaxf(p1.x + bb.z, 0.f); pv[i][3] = fmaxf(p1.y + bb.w, 0.f);
            }
            __syncthreads();
#pragma unroll
            for (int j = 0; j < 4; j++)
                *(float4*)&Ps[(c4 + j) * 68 + e4] = make_float4(pv[0][j], pv[1][j], pv[2][j], pv[3][j]);
        }
        __syncthreads();
        // decoder 64->4 + head
        int node = tid >> 2, c = tid & 3;
        float dec = b4v[c];
#pragma unroll 8
        for (int k = 0; k < 64; k++) dec += Ps[k * 68 + node] * W4[k * 4 + c];

        int n = n0 + node;
        int nc = min(n, NN - 1);
        float ev  = elev[nc];
        float g   = gl[nc];
        float h7  = g_hcur[nc * 8 + 7];
        float old = g_hcur[nc * 8 + 4 + c];
        __syncwarp();
        if (n < NN) {
            float ph = 0.5f * dec + 0.5f * (h7 - ev) + ev;
            float pc = fminf(ph, g);
            float pl = fmaxf(pc, ev);
            out[(size_t)n * 16 + sidx * 4 + c] = pl;
            g_hcur[n * 8 + c]     = old;
            g_hcur[n * 8 + 4 + c] = pc;
        }
    }
}

// ---------------- launch ----------------
extern "C" void kernel_launch(void* const* d_in, const int* in_sizes, int n_in,
                              void* d_out, int out_size) {
    const float* h0     = (const float*)d_in[0];
    const float* runoff = (const float*)d_in[1];
    const float* elev   = (const float*)d_in[2];
    const float* gl     = (const float*)d_in[3];
    const float* ef     = (const float*)d_in[4];
    const int*   eix    = (const int*)d_in[5];
    const float* We1 = (const float*)d_in[7],  *be1 = (const float*)d_in[8];
    const float* We2 = (const float*)d_in[9],  *be2 = (const float*)d_in[10];
    const float* Wm1 = (const float*)d_in[11], *bm1 = (const float*)d_in[12];
    const float* Wm2 = (const float*)d_in[13], *bm2 = (const float*)d_in[14];
    const float* Wu1 = (const float*)d_in[15], *bu1 = (const float*)d_in[16];
    const float* Wu2 = (const float*)d_in[17], *bu2 = (const float*)d_in[18];
    const float* Wd1 = (const float*)d_in[19], *bd1 = (const float*)d_in[20];
    const float* Wd2 = (const float*)d_in[21], *bd2 = (const float*)d_in[22];
    float* out = (float*)d_out;

    cudaFuncSetAttribute(k_fuse, cudaFuncAttributeMaxDynamicSharedMemorySize, SMEM_FUSE);
    cudaFuncSetAttribute(k_node, cudaFuncAttributeMaxDynamicSharedMemorySize, SMEM_ND);

    const int* src = eix;
    const int* tgt = eix + NE;

    k_init<<<(NN * 8 + 255) / 256, 256>>>(h0, src, tgt);
    k_deg<<<(NE + 255) / 256, 256>>>(src, tgt);
    k_allocprep<<<(20800 + NN + 255) / 256, 256>>>(We2, be2, Wm1, bm1, Wm2, bm2,
                                                   Wu1, bu1, Wu2, bu2, Wd1, bd1);
    k_fill<<<(NE + 255) / 256, 256>>>(src, tgt, ef);

    for (int s = 0; s < 4; s++) {
        int step = s * 4;
        k_qp1<<<592, 256>>>(We1, be1, runoff, elev, step);
        k_edge1<<<6250, 256>>>(We1);
        k_fuse<<<444, 256, SMEM_FUSE>>>();
        k_edge2<<<6250, 256>>>();
        k_node<<<444, 256, SMEM_ND>>>(elev, gl, Wd2, bd2, out, s);
    }
}

// round 17
// speedup vs baseline: 1.0946x; 1.0090x over previous
#include <cuda_runtime.h>
#include <cstdint>

#define NN 100000
#define NE 800000
typedef unsigned long long u64;

// ---------------- device scratch ----------------
__device__ __align__(16) float  g_hcur[NN * 8];
__device__ __align__(16) float g_qp[(size_t)NN * 128];  // Q1|Q2 (then P1|P2)
__device__ __align__(16) float g_u3[(size_t)NN * 64];   // cx@Wu1_top + bu1
__device__ __align__(16) float g_hsum[(size_t)NN * 64]; // Hsum1 then Hsum2
// CSR structures (built once per call; bucket order across nodes arbitrary)
__device__ int g_deg_src[NN], g_deg_tgt[NN];
__device__ int g_offs_src[NN], g_offs_tgt[NN];
__device__ int g_cur_src[NN], g_cur_tgt[NN];
__device__ int g_ctr[2];
__device__ float4 g_csr_src[NE];   // (tgt as int bits, ef0, ef1, ef2)
__device__ int    g_csr_tgt[NE];   // src
// folded weights
__device__ float g_wbig[64 * 192]; // We2 @ [Wm1_top | Wm1_bot | Wu1_top]
__device__ float g_bvec[192];      // be2 @ same
__device__ float g_cvec[192];      // [bm1 | 0 | bu1]
__device__ float g_w2u[4096];      // Wm2 @ Wu1[64:128]
__device__ float g_vb[64];         // bm2 @ Wu1[64:128]
__device__ float g_wud[4096];      // Wu2 @ Wd1
__device__ float g_bud[64];        // bu2 @ Wd1 + bd1

// ---------------- f32x2 helpers ----------------
__device__ __forceinline__ u64 pk2(float x) {
    u64 d; asm("mov.b64 %0, {%1, %1};" : "=l"(d) : "f"(x)); return d;
}
__device__ __forceinline__ u64 f2(u64 a, u64 b, u64 c) {
    u64 d; asm("fma.rn.f32x2 %0, %1, %2, %3;" : "=l"(d) : "l"(a), "l"(b), "l"(c)); return d;
}
__device__ __forceinline__ float2 up2(u64 a) {
    float2 r; asm("mov.b64 {%0, %1}, %2;" : "=f"(r.x), "=f"(r.y) : "l"(a)); return r;
}

// C[64 x cols] += A^T B ; A k-major As[k*AP+row], B Bs[k*BP+col]
template<int K, int AP, int BP>
__device__ __forceinline__ void mmacc(const float* As, const float* Bs,
                                      u64 acc[4][2], int e4, int c4) {
#pragma unroll 8
    for (int k = 0; k < K; k++) {
        float4 a = *(const float4*)(As + k * AP + e4);
        ulonglong2 b = *(const ulonglong2*)(Bs + k * BP + c4);
        u64 a0 = pk2(a.x), a1 = pk2(a.y), a2 = pk2(a.z), a3 = pk2(a.w);
        acc[0][0] = f2(a0, b.x, acc[0][0]); acc[0][1] = f2(a0, b.y, acc[0][1]);
        acc[1][0] = f2(a1, b.x, acc[1][0]); acc[1][1] = f2(a1, b.y, acc[1][1]);
        acc[2][0] = f2(a2, b.x, acc[2][0]); acc[2][1] = f2(a2, b.y, acc[2][1]);
        acc[3][0] = f2(a3, b.x, acc[3][0]); acc[3][1] = f2(a3, b.y, acc[3][1]);
    }
}

// ---------------- setup kernels ----------------
__global__ void k_init(const float* __restrict__ h0,
                       const int* __restrict__ src, const int* __restrict__ tgt) {
    int i = blockIdx.x * blockDim.x + threadIdx.x;
    if (i < NN) { g_deg_src[i] = 0; g_deg_tgt[i] = 0; }
    if (i == 0) { g_ctr[0] = 0; g_ctr[1] = 0; }
    if (i < NN * 8) g_hcur[i] = h0[i];
}
__global__ void k_deg(const int* __restrict__ src, const int* __restrict__ tgt) {
    int e = blockIdx.x * blockDim.x + threadIdx.x;
    if (e < NE) {
        atomicAdd(&g_deg_src[src[e]], 1);
        atomicAdd(&g_deg_tgt[tgt[e]], 1);
    }
}
// bump-alloc CSR ranges + fold weights, one launch (independent index ranges)
__global__ void k_allocprep(const float* __restrict__ We2, const float* __restrict__ be2,
                            const float* __restrict__ Wm1, const float* __restrict__ bm1,
                            const float* __restrict__ Wm2, const float* __restrict__ bm2,
                            const float* __restrict__ Wu1, const float* __restrict__ bu1,
                            const float* __restrict__ Wu2, const float* __restrict__ bu2,
                            const float* __restrict__ Wd1, const float* __restrict__ bd1) {
    int idx = blockIdx.x * blockDim.x + threadIdx.x;
    if (idx >= 20800 && idx < 20800 + NN) {
        int n = idx - 20800;
        int o0 = atomicAdd(&g_ctr[0], g_deg_src[n]);
        g_offs_src[n] = o0; g_cur_src[n] = o0;
        int o1 = atomicAdd(&g_ctr[1], g_deg_tgt[n]);
        g_offs_tgt[n] = o1; g_cur_tgt[n] = o1;
        return;
    }
    if (idx < 12288) {
        int g = idx >> 12, rem = idx & 4095;
        int r = rem >> 6, c = rem & 63;
        const float* W = (g == 0) ? Wm1 : (g == 1) ? (Wm1 + 64 * 64) : Wu1;
        float s = 0.f;
#pragma unroll 8
        for (int b = 0; b < 64; b++) s += We2[r * 64 + b] * W[b * 64 + c];
        g_wbig[r * 192 + g * 64 + c] = s;
    } else if (idx < 12480) {
        int j = idx - 12288;
        int g = j >> 6, c = j & 63;
        const float* W = (g == 0) ? Wm1 : (g == 1) ? (Wm1 + 64 * 64) : Wu1;
        float s = 0.f;
#pragma unroll 8
        for (int b = 0; b < 64; b++) s += be2[b] * W[b * 64 + c];
        g_bvec[j] = s;
        g_cvec[j] = (g == 0) ? bm1[c] : (g == 2) ? bu1[c] : 0.f;
    } else if (idx < 16576) {
        int k = idx - 12480;
        int a = k >> 6, c = k & 63;
        float s = 0.f;
#pragma unroll 8
        for (int b = 0; b < 64; b++) s += Wm2[a * 64 + b] * Wu1[(64 + b) * 64 + c];
        g_w2u[k] = s;
    } else if (idx < 16640) {
        int c = idx - 16576;
        float s = 0.f;
#pragma unroll 8
        for (int b = 0; b < 64; b++) s += bm2[b] * Wu1[(64 + b) * 64 + c];
        g_vb[c] = s;
    } else if (idx < 20736) {
        int k = idx - 16640;
        int a = k >> 6, c = k & 63;
        float s = 0.f;
#pragma unroll 8
        for (int b = 0; b < 64; b++) s += Wu2[a * 64 + b] * Wd1[b * 64 + c];
        g_wud[k] = s;
    } else if (idx < 20800) {
        int c = idx - 20736;
        float s = bd1[c];
#pragma unroll 8
        for (int b = 0; b < 64; b++) s += bu2[b] * Wd1[b * 64 + c];
        g_bud[c] = s;
    }
}
// CSR fill with coalesced ef staging through shared memory
__global__ void __launch_bounds__(256) k_fill(const int* __restrict__ src,
                                              const int* __restrict__ tgt,
                                              const float* __restrict__ ef) {
    __shared__ float efs[768];
    int e0 = blockIdx.x * 256;
    int tid = threadIdx.x;
    // coalesced load of 256 edges x 3 floats
#pragma unroll
    for (int j = 0; j < 3; j++) {
        int idx = j * 256 + tid;
        size_t g = (size_t)e0 * 3 + idx;
        efs[idx] = (g < (size_t)NE * 3) ? ef[g] : 0.f;
    }
    __syncthreads();
    int e = e0 + tid;
    if (e >= NE) return;
    int s = src[e], t = tgt[e];
    float f0 = efs[tid * 3], f1 = efs[tid * 3 + 1], f2v = efs[tid * 3 + 2];
    int p = atomicAdd(&g_cur_src[s], 1);
    g_csr_src[p] = make_float4(__int_as_float(t), f0, f1, f2v);
    int q = atomicAdd(&g_cur_tgt[t], 1);
    g_csr_tgt[q] = s;
}

// ------------- Q1 = nf@We1[3:24]+be1, Q2 = nf@We1[24:45]; nf built inline -------------
__global__ void __launch_bounds__(256) k_qp1(const float* __restrict__ We1,
                                             const float* __restrict__ be1,
                                             const float* __restrict__ runoff,
                                             const float* __restrict__ elev,
                                             int step) {
    __shared__ float Wq[24 * 128];
    __shared__ float A[24 * 64];
    __shared__ float b1s[64];
    const int tid = threadIdx.x;
    const int tx = tid & 15, ty = tid >> 4;
    const int c4 = tx * 4, e4 = ty * 4;

    for (int i = tid; i < 24 * 128; i += 256) {
        int r = i >> 7, c = i & 127;
        float v = 0.f;
        if (r < 21) v = (c < 64) ? We1[(3 + r) * 64 + c] : We1[(24 + r) * 64 + (c - 64)];
        Wq[i] = v;
    }
    if (tid < 64) b1s[tid] = be1[tid];

    const int ntiles = (NN + 63) / 64;
    for (int tile = blockIdx.x; tile < ntiles; tile += gridDim.x) {
        int n0 = tile * 64;
        __syncthreads();
        for (int i = tid; i < 384; i += 256) {
            int e = i & 63, q = i >> 6;
            int n = min(n0 + e, NN - 1);
            float4 v;
            if (q < 2)      v = *(const float4*)(g_hcur + n * 8 + q * 4);
            else if (q < 5) v = *(const float4*)(runoff + (size_t)n * 24 + step + (q - 2) * 4);
            else            v = make_float4(elev[n], 0.f, 0.f, 0.f);
            A[(q * 4 + 0) * 64 + e] = v.x; A[(q * 4 + 1) * 64 + e] = v.y;
            A[(q * 4 + 2) * 64 + e] = v.z; A[(q * 4 + 3) * 64 + e] = v.w;
        }
        __syncthreads();
        u64 acc0[4][2] = {}, acc1[4][2] = {};
        mmacc<24, 64, 128>(A, Wq, acc0, e4, c4);
        mmacc<24, 64, 128>(A, Wq + 64, acc1, e4, c4);
        float4 bb = *(const float4*)&b1s[c4];
#pragma unroll
        for (int i = 0; i < 4; i++) {
            int n = n0 + e4 + i;
            if (n < NN) {
                float2 p0 = up2(acc0[i][0]), p1 = up2(acc0[i][1]);
                *(float4*)(g_qp + (size_t)n * 128 + c4) =
                    make_float4(p0.x + bb.x, p0.y + bb.y, p1.x + bb.z, p1.y + bb.w);
                float2 r0 = up2(acc1[i][0]), r1 = up2(acc1[i][1]);
                *(float4*)(g_qp + (size_t)n * 128 + 64 + c4) =
                    make_float4(r0.x, r0.y, r1.x, r1.y);
            }
        }
    }
}

// ------------- edge pass 1 (4-way unrolled): Hsum1[n] = sum relu(Q1[n]+Q2[t]+ef@Wef) ------
__global__ void __launch_bounds__(256) k_edge1(const float* __restrict__ We1) {
    const int l = threadIdx.x & 15;
    const int gstride = gridDim.x * (blockDim.x >> 4);
    int n = blockIdx.x * (blockDim.x >> 4) + (threadIdx.x >> 4);
    const int c4 = l * 4;
    const float4 w0 = *(const float4*)(We1 + c4);
    const float4 w1 = *(const float4*)(We1 + 64 + c4);
    const float4 w2 = *(const float4*)(We1 + 128 + c4);
    const float4* __restrict__ gq = (const float4*)g_qp;

    for (; n < NN; n += gstride) {
        float4 q1 = gq[(size_t)n * 32 + l];
        int off = g_offs_src[n], end = off + g_deg_src[n];
        float4 acc = make_float4(0.f, 0.f, 0.f, 0.f);
        int i = off;
        for (; i + 4 <= end; i += 4) {
            float4 t0 = g_csr_src[i];
            float4 t1 = g_csr_src[i + 1];
            float4 t2 = g_csr_src[i + 2];
            float4 t3 = g_csr_src[i + 3];
            float4 a0 = gq[(size_t)__float_as_int(t0.x) * 32 + 16 + l];
            float4 a1 = gq[(size_t)__float_as_int(t1.x) * 32 + 16 + l];
            float4 a2 = gq[(size_t)__float_as_int(t2.x) * 32 + 16 + l];
            float4 a3 = gq[(size_t)__float_as_int(t3.x) * 32 + 16 + l];
            acc.x += fmaxf(q1.x + a0.x + t0.y * w0.x + t0.z * w1.x + t0.w * w2.x, 0.f);
            acc.y += fmaxf(q1.y + a0.y + t0.y * w0.y + t0.z * w1.y + t0.w * w2.y, 0.f);
            acc.z += fmaxf(q1.z + a0.z + t0.y * w0.z + t0.z * w1.z + t0.w * w2.z, 0.f);
            acc.w += fmaxf(q1.w + a0.w + t0.y * w0.w + t0.z * w1.w + t0.w * w2.w, 0.f);
            acc.x += fmaxf(q1.x + a1.x + t1.y * w0.x + t1.z * w1.x + t1.w * w2.x, 0.f);
            acc.y += fmaxf(q1.y + a1.y + t1.y * w0.y + t1.z * w1.y + t1.w * w2.y, 0.f);
            acc.z += fmaxf(q1.z + a1.z + t1.y * w0.z + t1.z * w1.z + t1.w * w2.z, 0.f);
            acc.w += fmaxf(q1.w + a1.w + t1.y * w0.w + t1.z * w1.w + t1.w * w2.w, 0.f);
            acc.x += fmaxf(q1.x + a2.x + t2.y * w0.x + t2.z * w1.x + t2.w * w2.x, 0.f);
            acc.y += fmaxf(q1.y + a2.y + t2.y * w0.y + t2.z * w1.y + t2.w * w2.y, 0.f);
            acc.z += fmaxf(q1.z + a2.z + t2.y * w0.z + t2.z * w1.z + t2.w * w2.z, 0.f);
            acc.w += fmaxf(q1.w + a2.w + t2.y * w0.w + t2.z * w1.w + t2.w * w2.w, 0.f);
            acc.x += fmaxf(q1.x + a3.x + t3.y * w0.x + t3.z * w1.x + t3.w * w2.x, 0.f);
            acc.y += fmaxf(q1.y + a3.y + t3.y * w0.y + t3.z * w1.y + t3.w * w2.y, 0.f);
            acc.z += fmaxf(q1.z + a3.z + t3.y * w0.z + t3.z * w1.z + t3.w * w2.z, 0.f);
            acc.w += fmaxf(q1.w + a3.w + t3.y * w0.w + t3.z * w1.w + t3.w * w2.w, 0.f);
        }
        for (; i < end; i++) {
            float4 te = g_csr_src[i];
            float4 q2 = gq[(size_t)__float_as_int(te.x) * 32 + 16 + l];
            acc.x += fmaxf(q1.x + q2.x + te.y * w0.x + te.z * w1.x + te.w * w2.x, 0.f);
            acc.y += fmaxf(q1.y + q2.y + te.y * w0.y + te.z * w1.y + te.w * w2.y, 0.f);
            acc.z += fmaxf(q1.z + q2.z + te.y * w0.z + te.z * w1.z + te.w * w2.z, 0.f);
            acc.w += fmaxf(q1.w + q2.w + te.y * w0.w + te.z * w1.w + te.w * w2.w, 0.f);
        }
        *(float4*)(g_hsum + (size_t)n * 64 + c4) = acc;
    }
}

// ------------- fused: [P1|P2|U3] = Hsum1 @ wbig + deg_src*bvec + cvec -------------
#define SMEM_FUSE ((12288 + 4352 + 192 + 192) * 4)
__global__ void __launch_bounds__(256) k_fuse() {
    extern __shared__ __align__(16) float sm[];
    float* Wb  = sm;            // 64x192
    float* A   = sm + 12288;    // 64x68
    float* bvs = sm + 16640;
    float* cvs = sm + 16832;

    const int tid = threadIdx.x;
    const int tx = tid & 15, ty = tid >> 4;
    const int c4 = tx * 4, e4 = ty * 4;

    for (int i = tid; i < 12288; i += 256) Wb[i] = g_wbig[i];
    if (tid < 192) { bvs[tid] = g_bvec[tid]; cvs[tid] = g_cvec[tid]; }

    const int ntiles = (NN + 63) / 64;
    for (int tile = blockIdx.x; tile < ntiles; tile += gridDim.x) {
        int n0 = tile * 64;
        __syncthreads();
        for (int i = tid; i < 1024; i += 256) {
            int e = i & 63, q = i >> 6;
            int n = min(n0 + e, NN - 1);
            float4 v = *(const float4*)(g_hsum + (size_t)n * 64 + q * 4);
            A[(q * 4 + 0) * 68 + e] = v.x; A[(q * 4 + 1) * 68 + e] = v.y;
            A[(q * 4 + 2) * 68 + e] = v.z; A[(q * 4 + 3) * 68 + e] = v.w;
        }
        __syncthreads();
        float degf[4];
#pragma unroll
        for (int i = 0; i < 4; i++) degf[i] = (float)g_deg_src[min(n0 + e4 + i, NN - 1)];
#pragma unroll
        for (int g = 0; g < 3; g++) {
            u64 acc[4][2] = {};
            mmacc<64, 68, 192>(A, Wb + g * 64, acc, e4, c4);
            float4 bv = *(const float4*)&bvs[g * 64 + c4];
            float4 cv = *(const float4*)&cvs[g * 64 + c4];
#pragma unroll
            for (int i = 0; i < 4; i++) {
                int n = n0 + e4 + i;
                if (n < NN) {
                    float2 p0 = up2(acc[i][0]), p1 = up2(acc[i][1]);
                    float4 o = make_float4(p0.x + degf[i] * bv.x + cv.x,
                                           p0.y + degf[i] * bv.y + cv.y,
                                           p1.x + degf[i] * bv.z + cv.z,
                                           p1.y + degf[i] * bv.w + cv.w);
                    if (g == 0)      *(float4*)(g_qp + (size_t)n * 128 + c4) = o;
                    else if (g == 1) *(float4*)(g_qp + (size_t)n * 128 + 64 + c4) = o;
                    else             *(float4*)(g_u3 + (size_t)n * 64 + c4) = o;
                }
            }
        }
    }
}

// ------------- edge pass 2 (4-way unrolled): Hsum2[n] = sum relu(P1[s]+P2[n]) -------------
__global__ void __launch_bounds__(256) k_edge2() {
    const int l = threadIdx.x & 15;
    const int gstride = gridDim.x * (blockDim.x >> 4);
    int n = blockIdx.x * (blockDim.x >> 4) + (threadIdx.x >> 4);
    const float4* __restrict__ gq = (const float4*)g_qp;

    for (; n < NN; n += gstride) {
        float4 p2 = gq[(size_t)n * 32 + 16 + l];
        int off = g_offs_tgt[n], end = off + g_deg_tgt[n];
        float4 acc = make_float4(0.f, 0.f, 0.f, 0.f);
        int i = off;
        for (; i + 4 <= end; i += 4) {
            int s0 = g_csr_tgt[i];
            int s1 = g_csr_tgt[i + 1];
            int s2 = g_csr_tgt[i + 2];
            int s3 = g_csr_tgt[i + 3];
            float4 a0 = gq[(size_t)s0 * 32 + l];
            float4 a1 = gq[(size_t)s1 * 32 + l];
            float4 a2 = gq[(size_t)s2 * 32 + l];
            float4 a3 = gq[(size_t)s3 * 32 + l];
            acc.x += fmaxf(a0.x + p2.x, 0.f) + fmaxf(a1.x + p2.x, 0.f)
                   + fmaxf(a2.x + p2.x, 0.f) + fmaxf(a3.x + p2.x, 0.f);
            acc.y += fmaxf(a0.y + p2.y, 0.f) + fmaxf(a1.y + p2.y, 0.f)
                   + fmaxf(a2.y + p2.y, 0.f) + fmaxf(a3.y + p2.y, 0.f);
            acc.z += fmaxf(a0.z + p2.z, 0.f) + fmaxf(a1.z + p2.z, 0.f)
                   + fmaxf(a2.z + p2.z, 0.f) + fmaxf(a3.z + p2.z, 0.f);
            acc.w += fmaxf(a0.w + p2.w, 0.f) + fmaxf(a1.w + p2.w, 0.f)
                   + fmaxf(a2.w + p2.w, 0.f) + fmaxf(a3.w + p2.w, 0.f);
        }
        for (; i < end; i++) {
            int s = g_csr_tgt[i];
            float4 p1 = gq[(size_t)s * 32 + l];
            acc.x += fmaxf(p1.x + p2.x, 0.f);
            acc.y += fmaxf(p1.y + p2.y, 0.f);
            acc.z += fmaxf(p1.z + p2.z, 0.f);
            acc.w += fmaxf(p1.w + p2.w, 0.f);
        }
        *(float4*)(g_hsum + (size_t)n * 64 + l * 4) = acc;
    }
}

// ---------------- node: 2 GEMMs (w2u, wud) + decoder + head ----------------
#define SMEM_ND (17296 * 4)
__global__ void __launch_bounds__(256) k_node(
    const float* __restrict__ elev, const float* __restrict__ gl,
    const float* __restrict__ Wd2, const float* __restrict__ bd2,
    float* __restrict__ out, int sidx)
{
    extern __shared__ __align__(16) float sm[];
    float* W1   = sm;          float* W2  = sm + 4096;
    float* W4   = sm + 8192;
    float* vbs  = sm + 8448;   float* budv = sm + 8512;
    float* b4v  = sm + 8576;
    float* A    = sm + 8592;   float* Ps = A;
    float* Hs   = sm + 12944;

    const int tid = threadIdx.x;
    const int tx = tid & 15, ty = tid >> 4;
    const int c4 = tx * 4, e4 = ty * 4;

    for (int i = tid; i < 4096; i += 256) { W1[i] = g_w2u[i]; W2[i] = g_wud[i]; }
    if (tid < 256) W4[tid] = Wd2[tid];
    if (tid < 64) { vbs[tid] = g_vb[tid]; budv[tid] = g_bud[tid]; }
    if (tid < 4) b4v[tid] = bd2[tid];

    const int ntiles = (NN + 63) / 64;
    for (int tile = blockIdx.x; tile < ntiles; tile += gridDim.x) {
        int n0 = tile * 64;
        __syncthreads();
        for (int i = tid; i < 1024; i += 256) {
            int e = i & 63, q = i >> 6;
            int n = min(n0 + e, NN - 1);
            float4 v = *(const float4*)(g_hsum + (size_t)n * 64 + q * 4);
            A[(q * 4 + 0) * 68 + e] = v.x; A[(q * 4 + 1) * 68 + e] = v.y;
            A[(q * 4 + 2) * 68 + e] = v.z; A[(q * 4 + 3) * 68 + e] = v.w;
        }
        __syncthreads();
        u64 acc[4][2] = {};
        mmacc<64, 68, 64>(A, W1, acc, e4, c4);
        {
            float4 vv = *(const float4*)&vbs[c4];
            float hv[4][4];
#pragma unroll
            for (int i = 0; i < 4; i++) {
                int nc = min(n0 + e4 + i, NN - 1);
                float degf = (float)g_deg_tgt[nc];
                float4 u3 = *(const float4*)(g_u3 + (size_t)nc * 64 + c4);
                float2 p0 = up2(acc[i][0]), p1 = up2(acc[i][1]);
                hv[i][0] = fmaxf(p0.x + u3.x + degf * vv.x, 0.f);
                hv[i][1] = fmaxf(p0.y + u3.y + degf * vv.y, 0.f);
                hv[i][2] = fmaxf(p1.x + u3.z + degf * vv.z, 0.f);
                hv[i][3] = fmaxf(p1.y + u3.w + degf * vv.w, 0.f);
            }
            __syncthreads();
#pragma unroll
            for (int j = 0; j < 4; j++)
                *(float4*)&Hs[(c4 + j) * 68 + e4] = make_float4(hv[0][j], hv[1][j], hv[2][j], hv[3][j]);
        }
        __syncthreads();
        u64 acc2[4][2] = {};
        mmacc<64, 68, 64>(Hs, W2, acc2, e4, c4);
        {
            float4 bb = *(const float4*)&budv[c4];
            float pv[4][4];
#pragma unroll
            for (int i = 0; i < 4; i++) {
                float2 p0 = up2(acc2[i][0]), p1 = up2(acc2[i][1]);
                pv[i][0] = fmaxf(p0.x + bb.x, 0.f); pv[i][1] = fmaxf(p0.y + bb.y, 0.f);
                pv[i][2] = fmaxf(p1.x + bb.z, 0.f); pv[i][3] = fmaxf(p1.y + bb.w, 0.f);
            }
            __syncthreads();
#pragma unroll
            for (int j = 0; j < 4; j++)
                *(float4*)&Ps[(c4 + j) * 68 + e4] = make_float4(pv[0][j], pv[1][j], pv[2][j], pv[3][j]);
        }
        __syncthreads();
        // decoder 64->4 + head
        int node = tid >> 2, c = tid & 3;
        float dec = b4v[c];
#pragma unroll 8
        for (int k = 0; k < 64; k++) dec += Ps[k * 68 + node] * W4[k * 4 + c];

        int n = n0 + node;
        int nc = min(n, NN - 1);
        float ev  = elev[nc];
        float g   = gl[nc];
        float h7  = g_hcur[nc * 8 + 7];
        float old = g_hcur[nc * 8 + 4 + c];
        __syncwarp();
        if (n < NN) {
            float ph = 0.5f * dec + 0.5f * (h7 - ev) + ev;
            float pc = fminf(ph, g);
            float pl = fmaxf(pc, ev);
            out[(size_t)n * 16 + sidx * 4 + c] = pl;
            g_hcur[n * 8 + c]     = old;
            g_hcur[n * 8 + 4 + c] = pc;
        }
    }
}

// ---------------- launch ----------------
extern "C" void kernel_launch(void* const* d_in, const int* in_sizes, int n_in,
                              void* d_out, int out_size) {
    const float* h0     = (const float*)d_in[0];
    const float* runoff = (const float*)d_in[1];
    const float* elev   = (const float*)d_in[2];
    const float* gl     = (const float*)d_in[3];
    const float* ef     = (const float*)d_in[4];
    const int*   eix    = (const int*)d_in[5];
    const float* We1 = (const float*)d_in[7],  *be1 = (const float*)d_in[8];
    const float* We2 = (const float*)d_in[9],  *be2 = (const float*)d_in[10];
    const float* Wm1 = (const float*)d_in[11], *bm1 = (const float*)d_in[12];
    const float* Wm2 = (const float*)d_in[13], *bm2 = (const float*)d_in[14];
    const float* Wu1 = (const float*)d_in[15], *bu1 = (const float*)d_in[16];
    const float* Wu2 = (const float*)d_in[17], *bu2 = (const float*)d_in[18];
    const float* Wd1 = (const float*)d_in[19], *bd1 = (const float*)d_in[20];
    const float* Wd2 = (const float*)d_in[21], *bd2 = (const float*)d_in[22];
    float* out = (float*)d_out;

    cudaFuncSetAttribute(k_fuse, cudaFuncAttributeMaxDynamicSharedMemorySize, SMEM_FUSE);
    cudaFuncSetAttribute(k_node, cudaFuncAttributeMaxDynamicSharedMemorySize, SMEM_ND);

    const int* src = eix;
    const int* tgt = eix + NE;

    k_init<<<(NN * 8 + 255) / 256, 256>>>(h0, src, tgt);
    k_deg<<<(NE + 255) / 256, 256>>>(src, tgt);
    k_allocprep<<<(20800 + NN + 255) / 256, 256>>>(We2, be2, Wm1, bm1, Wm2, bm2,
                                                   Wu1, bu1, Wu2, bu2, Wd1, bd1);
    k_fill<<<(NE + 255) / 256, 256>>>(src, tgt, ef);

    for (int s = 0; s < 4; s++) {
        int step = s * 4;
        k_qp1<<<592, 256>>>(We1, be1, runoff, elev, step);
        k_edge1<<<6250, 256>>>(We1);
        k_fuse<<<444, 256, SMEM_FUSE>>>();
        k_edge2<<<6250, 256>>>();
        k_node<<<444, 256, SMEM_ND>>>(elev, gl, Wd2, bd2, out, s);
    }
}